// round 2
// baseline (speedup 1.0000x reference)
#include <cuda_runtime.h>
#include <math.h>

#define NB 8
#define SEQ 512
#define DM 1024
#define NH 16
#define HDIM 64

// Scratch (static __device__ arrays: allocation-guard safe)
__device__ float g_pos[1024 * 64];      // relative positional table [2S][64]
__device__ float g_E[16 * 1024];        // (r_w - r_r) . pos[j] per head
__device__ float g_qv[4096 * 2048];     // x @ Wqv

// ---------------------------------------------------------------------------
// pos[j][i] : j in [0,1024), posval = j-512; cols 0..31 sin, 32..63 cos
// freq_i = exp(-i * ln(10000)/31)
// ---------------------------------------------------------------------------
__global__ void k_pos() {
    int idx = blockIdx.x * blockDim.x + threadIdx.x;
    if (idx >= 1024 * 64) return;
    int j = idx >> 6;
    int i = idx & 63;
    const float C = -logf(10000.0f) / 31.0f;
    int ii = (i < 32) ? i : (i - 32);
    float freq = expf((float)ii * C);
    float arg = (float)(j - 512) * freq;
    g_pos[idx] = (i < 32) ? sinf(arg) : cosf(arg);
}

// ---------------------------------------------------------------------------
// E[h][j] = sum_d (r_w[h][d] - r_r[h][d]) * pos[j][d]
// ---------------------------------------------------------------------------
__global__ void k_E(const float* __restrict__ rr, const float* __restrict__ rw) {
    int j = blockIdx.x * blockDim.x + threadIdx.x;   // 0..1023
    int h = blockIdx.y;
    float s = 0.f;
#pragma unroll 8
    for (int d = 0; d < 64; d++)
        s += (rw[h * 64 + d] - rr[h * 64 + d]) * g_pos[j * 64 + d];
    g_E[h * 1024 + j] = s;
}

// ---------------------------------------------------------------------------
// qv = x @ Wqv   (M=4096, K=1024, N=2048), fp32 SIMT 128x128x16 tiles
// ---------------------------------------------------------------------------
__global__ void __launch_bounds__(256) k_gemm(const float* __restrict__ A,
                                              const float* __restrict__ Bw) {
    __shared__ float As[16][132];   // transposed: As[k][m]
    __shared__ float Bs[16][132];   // Bs[k][n]
    const int tid = threadIdx.x;
    const int m0 = blockIdx.y * 128;
    const int n0 = blockIdx.x * 128;
    const int tm = tid >> 4, tn = tid & 15;
    float acc[8][8] = {};
    for (int k0 = 0; k0 < 1024; k0 += 16) {
#pragma unroll
        for (int r = 0; r < 2; r++) {
            int idx = tid + r * 256;           // 0..511 (128 rows x 4 float4)
            int row = idx >> 2;
            int c4 = (idx & 3) * 4;
            float4 v = *(const float4*)(A + (size_t)(m0 + row) * 1024 + k0 + c4);
            As[c4 + 0][row] = v.x;
            As[c4 + 1][row] = v.y;
            As[c4 + 2][row] = v.z;
            As[c4 + 3][row] = v.w;
        }
#pragma unroll
        for (int r = 0; r < 2; r++) {
            int idx = tid + r * 256;           // 16 rows x 32 float4
            int row = idx >> 5;
            int c32 = (idx & 31) * 4;
            *(float4*)&Bs[row][c32] =
                *(const float4*)(Bw + (size_t)(k0 + row) * 2048 + n0 + c32);
        }
        __syncthreads();
#pragma unroll
        for (int kk = 0; kk < 16; kk++) {
            float4 a0 = *(const float4*)&As[kk][tm * 8];
            float4 a1 = *(const float4*)&As[kk][tm * 8 + 4];
            float4 b0 = *(const float4*)&Bs[kk][tn * 8];
            float4 b1 = *(const float4*)&Bs[kk][tn * 8 + 4];
            float av[8] = {a0.x, a0.y, a0.z, a0.w, a1.x, a1.y, a1.z, a1.w};
            float bv[8] = {b0.x, b0.y, b0.z, b0.w, b1.x, b1.y, b1.z, b1.w};
#pragma unroll
            for (int i = 0; i < 8; i++)
#pragma unroll
                for (int j = 0; j < 8; j++)
                    acc[i][j] += av[i] * bv[j];
        }
        __syncthreads();
    }
#pragma unroll
    for (int i = 0; i < 8; i++) {
        size_t rowoff = (size_t)(m0 + tm * 8 + i) * 2048 + n0 + tn * 8;
        float4 v0 = {acc[i][0], acc[i][1], acc[i][2], acc[i][3]};
        float4 v1 = {acc[i][4], acc[i][5], acc[i][6], acc[i][7]};
        *(float4*)(g_qv + rowoff) = v0;
        *(float4*)(g_qv + rowoff + 4) = v1;
    }
}

// ---------------------------------------------------------------------------
// Fused attention: per CTA one (b,h) and a 64-row q tile. Streaming over
// 64-col k tiles with online softmax.
// score[q,k] = A1.K[k] + A1.pos[512+k-q] + E[h,512+k-q]   (A1 = q + r_r)
// mask: attn*m - (1-m)*1e8
// Smem (floats): QrrT[64][68] | KT/P[64][68] | posT[64][132] (V aliases)
//                | E[128] | m,l,scale,maskf [64 each]   -> 70144 bytes
// ---------------------------------------------------------------------------
__global__ void __launch_bounds__(256) k_attn(const float* __restrict__ x,
                                              const int* __restrict__ mask,
                                              const float* __restrict__ rr,
                                              float* __restrict__ out) {
    extern __shared__ float sm[];
    float* QrrT = sm;                 // [64 d][68]   A1 transposed
    float* KT   = sm + 4352;          // [64 d][68]   (aliased by P[64 q][68])
    float* posT = sm + 8704;          // [64 d][132]  (aliased by V[64 k][68])
    float* Es   = sm + 17152;         // 128
    float* msm  = sm + 17280;         // 64
    float* lsm  = sm + 17344;         // 64
    float* scsm = sm + 17408;         // 64
    float* mksm = sm + 17472;         // 64

    const int tid = threadIdx.x;
    const int bh = blockIdx.y;
    const int b = bh >> 4, h = bh & 15;
    const int q0 = blockIdx.x * 64;
    const int qg = tid >> 4, kg = tid & 15;   // 16x16; kg doubles as dg in O-phase

    // Load Q tile + r_r_bias, transposed
    {
        const float* qb = g_qv + (size_t)(b * SEQ + q0) * 2048 + h * 64;
#pragma unroll
        for (int r = 0; r < 4; r++) {
            int idx = tid + r * 256;          // 64 rows x 16 float4
            int row = idx >> 4;
            int c4 = (idx & 15) * 4;
            float4 v = *(const float4*)(qb + (size_t)row * 2048 + c4);
            float4 bb = *(const float4*)(rr + h * 64 + c4);
            QrrT[(c4 + 0) * 68 + row] = v.x + bb.x;
            QrrT[(c4 + 1) * 68 + row] = v.y + bb.y;
            QrrT[(c4 + 2) * 68 + row] = v.z + bb.z;
            QrrT[(c4 + 3) * 68 + row] = v.w + bb.w;
        }
    }
    if (tid < 64) { msm[tid] = -1e30f; lsm[tid] = 0.f; }

    float o[4][4] = {};

    for (int k0 = 0; k0 < SEQ; k0 += 64) {
        const int base = 449 + k0 - q0;       // pos window start (1..897)
        __syncthreads();                       // prev P/V consumers done

        // K tile transposed (K[b,h,s,d] = x[b,s,h*64+d])
        {
            const float* kb = x + (size_t)(b * SEQ + k0) * DM + h * 64;
#pragma unroll
            for (int r = 0; r < 4; r++) {
                int idx = tid + r * 256;
                int row = idx >> 4;
                int c4 = (idx & 15) * 4;
                float4 v = *(const float4*)(kb + (size_t)row * DM + c4);
                KT[(c4 + 0) * 68 + row] = v.x;
                KT[(c4 + 1) * 68 + row] = v.y;
                KT[(c4 + 2) * 68 + row] = v.z;
                KT[(c4 + 3) * 68 + row] = v.w;
            }
        }
        // pos window transposed: rows [base, base+126]
        {
#pragma unroll
            for (int r = 0; r < 8; r++) {
                int idx = tid + r * 256;       // up to 128 rows x 16 float4
                int row = idx >> 4;
                int c4 = (idx & 15) * 4;
                if (row < 127) {
                    float4 v = *(const float4*)(g_pos + (size_t)(base + row) * 64 + c4);
                    posT[(c4 + 0) * 132 + row] = v.x;
                    posT[(c4 + 1) * 132 + row] = v.y;
                    posT[(c4 + 2) * 132 + row] = v.z;
                    posT[(c4 + 3) * 132 + row] = v.w;
                }
            }
        }
        if (tid < 128) Es[tid] = (tid < 127) ? g_E[h * 1024 + base + tid] : 0.f;
        if (tid < 64)  mksm[tid] = (float)mask[b * SEQ + k0 + tid];
        __syncthreads();

        // --- S = A1.K^T + A1.pos(shifted) ---
        float c[4][4] = {};
        const int w = 60 + 4 * (kg - qg);     // aligned 7-row pos window
#pragma unroll 2
        for (int d = 0; d < 64; d++) {
            float4 a4 = *(const float4*)(QrrT + d * 68 + qg * 4);
            float4 k4 = *(const float4*)(KT + d * 68 + kg * 4);
            float4 p0 = *(const float4*)(posT + d * 132 + w);
            float4 p1 = *(const float4*)(posT + d * 132 + w + 4);
            float av[4] = {a4.x, a4.y, a4.z, a4.w};
            float kv[4] = {k4.x, k4.y, k4.z, k4.w};
            float pv[8] = {p0.x, p0.y, p0.z, p0.w, p1.x, p1.y, p1.z, p1.w};
#pragma unroll
            for (int i = 0; i < 4; i++)
#pragma unroll
                for (int j = 0; j < 4; j++) {
                    c[i][j] += av[i] * kv[j];
                    c[i][j] += av[i] * pv[3 + j - i];
                }
        }
#pragma unroll
        for (int i = 0; i < 4; i++)
#pragma unroll
            for (int j = 0; j < 4; j++) {
                float cc = c[i][j] + Es[w + 3 + j - i];
                float mv = mksm[kg * 4 + j];
                c[i][j] = cc * mv - (1.f - mv) * 1e8f;
            }

        // --- row max across the 16 kg lanes (same half-warp) ---
        float rmax[4];
#pragma unroll
        for (int i = 0; i < 4; i++)
            rmax[i] = fmaxf(fmaxf(c[i][0], c[i][1]), fmaxf(c[i][2], c[i][3]));
#pragma unroll
        for (int off = 8; off >= 1; off >>= 1)
#pragma unroll
            for (int i = 0; i < 4; i++)
                rmax[i] = fmaxf(rmax[i], __shfl_xor_sync(0xffffffffu, rmax[i], off));
        float mold[4], mnew[4];
#pragma unroll
        for (int i = 0; i < 4; i++) {
            mold[i] = msm[qg * 4 + i];
            mnew[i] = fmaxf(mold[i], rmax[i]);
        }
        __syncthreads();                       // all done reading KT/posT

        // --- P = exp(S - m_new), write into KT region; row sums ---
        float rsum[4] = {0.f, 0.f, 0.f, 0.f};
#pragma unroll
        for (int i = 0; i < 4; i++) {
            float4 pr;
            pr.x = __expf(c[i][0] - mnew[i]);
            pr.y = __expf(c[i][1] - mnew[i]);
            pr.z = __expf(c[i][2] - mnew[i]);
            pr.w = __expf(c[i][3] - mnew[i]);
            rsum[i] += pr.x + pr.y + pr.z + pr.w;
            *(float4*)(KT + (qg * 4 + i) * 68 + kg * 4) = pr;
        }
#pragma unroll
        for (int off = 8; off >= 1; off >>= 1)
#pragma unroll
            for (int i = 0; i < 4; i++)
                rsum[i] += __shfl_xor_sync(0xffffffffu, rsum[i], off);
        if (kg == 0) {
#pragma unroll
            for (int i = 0; i < 4; i++) {
                int q = qg * 4 + i;
                float s = __expf(mold[i] - mnew[i]);
                msm[q] = mnew[i];
                scsm[q] = s;
                lsm[q] = lsm[q] * s + rsum[i];
            }
        }
        // --- load V into posT region (stride 68, natural [k][d]) ---
        {
            const float* vb = g_qv + (size_t)(b * SEQ + k0) * 2048 + 1024 + h * 64;
#pragma unroll
            for (int r = 0; r < 4; r++) {
                int idx = tid + r * 256;
                int row = idx >> 4;
                int c4 = (idx & 15) * 4;
                float4 v = *(const float4*)(vb + (size_t)row * 2048 + c4);
                *(float4*)(posT + row * 68 + c4) = v;
            }
        }
        __syncthreads();

        // --- O = O*scale + P @ V ---
#pragma unroll
        for (int i = 0; i < 4; i++) {
            float s = scsm[qg * 4 + i];
#pragma unroll
            for (int j = 0; j < 4; j++) o[i][j] *= s;
        }
#pragma unroll 2
        for (int kk = 0; kk < 64; kk++) {
            float4 v = *(const float4*)(posT + kk * 68 + kg * 4);
            float pvv[4];
#pragma unroll
            for (int i = 0; i < 4; i++) pvv[i] = KT[(qg * 4 + i) * 68 + kk];
#pragma unroll
            for (int i = 0; i < 4; i++) {
                o[i][0] += pvv[i] * v.x;
                o[i][1] += pvv[i] * v.y;
                o[i][2] += pvv[i] * v.z;
                o[i][3] += pvv[i] * v.w;
            }
        }
    }

    // epilogue: out[b, q, h*64+d] = O / l
#pragma unroll
    for (int i = 0; i < 4; i++) {
        int q = q0 + qg * 4 + i;
        float inv = 1.f / lsm[qg * 4 + i];
        float4 r;
        r.x = o[i][0] * inv;
        r.y = o[i][1] * inv;
        r.z = o[i][2] * inv;
        r.w = o[i][3] * inv;
        *(float4*)(out + ((size_t)(b * SEQ) + q) * DM + h * 64 + kg * 4) = r;
    }
}

// ---------------------------------------------------------------------------
extern "C" void kernel_launch(void* const* d_in, const int* in_sizes, int n_in,
                              void* d_out, int out_size) {
    const float* x   = (const float*)d_in[0];
    const int*   msk = (const int*)d_in[1];
    const float* Wqv = (const float*)d_in[2];
    const float* rr  = (const float*)d_in[3];
    const float* rw  = (const float*)d_in[4];
    float* out = (float*)d_out;

    cudaFuncSetAttribute(k_attn, cudaFuncAttributeMaxDynamicSharedMemorySize, 70144);

    k_pos<<<256, 256>>>();
    k_E<<<dim3(4, 16), 256>>>(rr, rw);
    k_gemm<<<dim3(16, 32), 256>>>(x, Wqv);
    k_attn<<<dim3(8, 128), 256, 70144>>>(x, msk, rr, out);
}

// round 6
// speedup vs baseline: 1.2765x; 1.2765x over previous
#include <cuda_runtime.h>
#include <cuda_bf16.h>
#include <math.h>
#include <cstdint>

#define NB 8
#define SEQ 512
#define DM 1024
#define NH 16
#define HDIM 64

// ---------------- scratch (static __device__: allocation-guard safe) -------
__device__ float g_pos[1024 * 64];            // relative positional table
__device__ float g_E[16 * 1024];              // (r_w - r_r) . pos[j]
__device__ float g_qv[4096 * 2048];           // x @ Wqv (fp32)
__device__ __nv_bfloat16 g_xhi[4096 * 1024];  // x split hi
__device__ __nv_bfloat16 g_xlo[4096 * 1024];  // x split lo
__device__ __nv_bfloat16 g_whi[2048 * 1024];  // Wqv^T split hi  [n][k]
__device__ __nv_bfloat16 g_wlo[2048 * 1024];  // Wqv^T split lo

// ---------------- helpers ---------------------------------------------------
__device__ __forceinline__ uint32_t smem_u32(const void* p) {
    uint32_t a;
    asm("{ .reg .u64 t; cvta.to.shared.u64 t, %1; cvt.u32.u64 %0, t; }" : "=r"(a) : "l"(p));
    return a;
}
__device__ __forceinline__ void ldmatrix_x4(uint32_t* r, uint32_t addr) {
    asm volatile("ldmatrix.sync.aligned.m8n8.x4.shared.b16 {%0,%1,%2,%3}, [%4];"
                 : "=r"(r[0]), "=r"(r[1]), "=r"(r[2]), "=r"(r[3]) : "r"(addr));
}
__device__ __forceinline__ void mma_bf16(float* c, const uint32_t* a, const uint32_t* b) {
    asm volatile("mma.sync.aligned.m16n8k16.row.col.f32.bf16.bf16.f32 "
                 "{%0,%1,%2,%3}, {%4,%5,%6,%7}, {%8,%9}, {%0,%1,%2,%3};"
                 : "+f"(c[0]), "+f"(c[1]), "+f"(c[2]), "+f"(c[3])
                 : "r"(a[0]), "r"(a[1]), "r"(a[2]), "r"(a[3]), "r"(b[0]), "r"(b[1]));
}
__device__ __forceinline__ void cp_async16(uint32_t saddr, const void* gaddr) {
    asm volatile("cp.async.cg.shared.global [%0], [%1], 16;" ::"r"(saddr), "l"(gaddr));
}
#define CP_COMMIT() asm volatile("cp.async.commit_group;" ::: "memory")
#define CP_WAIT(N) asm volatile("cp.async.wait_group %0;" ::"n"(N) : "memory")

// ---------------------------------------------------------------------------
// prep: bf16 hi/lo split of x
// ---------------------------------------------------------------------------
__global__ void k_cvt_x(const float* __restrict__ x) {
    int i = (blockIdx.x * blockDim.x + threadIdx.x) * 4;
    float4 v = *(const float4*)(x + i);
    float a[4] = {v.x, v.y, v.z, v.w};
    __nv_bfloat16 h[4], l[4];
#pragma unroll
    for (int j = 0; j < 4; j++) {
        h[j] = __float2bfloat16(a[j]);
        l[j] = __float2bfloat16(a[j] - __bfloat162float(h[j]));
    }
    *(uint2*)(g_xhi + i) = *(uint2*)h;
    *(uint2*)(g_xlo + i) = *(uint2*)l;
}

// prep: Wqv^T with bf16 hi/lo split (tiled transpose)
__global__ void k_cvt_w(const float* __restrict__ W) {
    __shared__ float t[32][33];
    int tx = threadIdx.x, ty = threadIdx.y;
    int n0 = blockIdx.x * 32, k0 = blockIdx.y * 32;
#pragma unroll
    for (int i = 0; i < 4; i++)
        t[ty + i * 8][tx] = W[(size_t)(k0 + ty + i * 8) * 2048 + n0 + tx];
    __syncthreads();
#pragma unroll
    for (int i = 0; i < 4; i++) {
        int n = n0 + ty + i * 8;
        float v = t[tx][ty + i * 8];
        __nv_bfloat16 h = __float2bfloat16(v);
        g_whi[(size_t)n * 1024 + k0 + tx] = h;
        g_wlo[(size_t)n * 1024 + k0 + tx] = __float2bfloat16(v - __bfloat162float(h));
    }
}

// ---------------------------------------------------------------------------
// pos table + E table
// ---------------------------------------------------------------------------
__global__ void k_pos() {
    int idx = blockIdx.x * blockDim.x + threadIdx.x;
    if (idx >= 1024 * 64) return;
    int j = idx >> 6;
    int i = idx & 63;
    const float C = -logf(10000.0f) / 31.0f;
    int ii = (i < 32) ? i : (i - 32);
    float freq = expf((float)ii * C);
    float arg = (float)(j - 512) * freq;
    g_pos[idx] = (i < 32) ? sinf(arg) : cosf(arg);
}

__global__ void k_E(const float* __restrict__ rr, const float* __restrict__ rw) {
    int j = blockIdx.x * blockDim.x + threadIdx.x;
    int h = blockIdx.y;
    float s = 0.f;
#pragma unroll 8
    for (int d = 0; d < 64; d++)
        s += (rw[h * 64 + d] - rr[h * 64 + d]) * g_pos[j * 64 + d];
    g_E[h * 1024 + j] = s;
}

// ---------------------------------------------------------------------------
// qv = x @ Wqv via mma.sync bf16 2-split (Ah*Bh + Ah*Bl + Al*Bh), fp32 accum.
// CTA tile 128x128, BK=32, 8 warps (warp tile 32x64), cp.async 2-stage.
// SMEM tiles K-major, row stride 72 bf16 (144B) -> conflict-free ldmatrix.
// Stage layout: Ah[128][72] | Al | Bh | Bl  (18432 B each, 73728 B/stage)
// ---------------------------------------------------------------------------
#define RS 72
#define TILE_B 18432
#define STAGE_B 73728

__global__ void __launch_bounds__(256) k_mm() {
    extern __shared__ __nv_bfloat16 smb[];
    const uint32_t sb = smem_u32(smb);
    const int tid = threadIdx.x;
    const int wid = tid >> 5, lane = tid & 31;
    const int m0 = blockIdx.y * 128, n0 = blockIdx.x * 128;

    const __nv_bfloat16* src0 = g_xhi + (size_t)m0 * 1024;
    const __nv_bfloat16* src1 = g_xlo + (size_t)m0 * 1024;
    const __nv_bfloat16* src2 = g_whi + (size_t)n0 * 1024;
    const __nv_bfloat16* src3 = g_wlo + (size_t)n0 * 1024;

    // per-thread prefetch slot: thread covers 8 uint4s, 2 per tile
    const int p_row = tid >> 1;            // 0..127
    const int p_c0 = (tid & 1) * 2;        // uint4 index 0 or 2 within row

    // warp tiling: 4 warps along M, 2 along N
    const int wm = wid >> 1, wn = wid & 1;
    const int m_base = wm * 32, n_base = wn * 64;
    const int lr = lane & 7, q = lane >> 3;

    float acc[2][8][4];
#pragma unroll
    for (int i = 0; i < 2; i++)
#pragma unroll
        for (int j = 0; j < 8; j++)
#pragma unroll
            for (int k = 0; k < 4; k++) acc[i][j][k] = 0.f;

    // ---- prefetch for kt into stage: straight-line, no captures ----
#define PREFETCH(KT, STAGE)                                                              \
    do {                                                                                 \
        const int _k0 = (KT) * 32;                                                       \
        const uint32_t _stg = sb + (STAGE) * STAGE_B;                                    \
        const uint32_t _soff = (uint32_t)(p_row * RS) * 2 + p_c0 * 16;                   \
        const size_t _goff = (size_t)p_row * 1024 + _k0 + p_c0 * 8;                      \
        cp_async16(_stg + _soff, src0 + _goff);                                          \
        cp_async16(_stg + _soff + 16, src0 + _goff + 8);                                 \
        cp_async16(_stg + TILE_B + _soff, src1 + _goff);                                 \
        cp_async16(_stg + TILE_B + _soff + 16, src1 + _goff + 8);                        \
        cp_async16(_stg + 2 * TILE_B + _soff, src2 + _goff);                             \
        cp_async16(_stg + 2 * TILE_B + _soff + 16, src2 + _goff + 8);                    \
        cp_async16(_stg + 3 * TILE_B + _soff, src3 + _goff);                             \
        cp_async16(_stg + 3 * TILE_B + _soff + 16, src3 + _goff + 8);                    \
    } while (0)

    PREFETCH(0, 0);
    CP_COMMIT();

    for (int kt = 0; kt < 32; kt++) {
        const int stage = kt & 1;
        if (kt + 1 < 32) {
            PREFETCH(kt + 1, stage ^ 1);
            CP_COMMIT();
            CP_WAIT(1);
        } else {
            CP_WAIT(0);
        }
        __syncthreads();

        const uint32_t stg = sb + stage * STAGE_B;
        const uint32_t bAh = stg, bAl = stg + TILE_B;
        const uint32_t bBh = stg + 2 * TILE_B, bBl = stg + 3 * TILE_B;

#pragma unroll
        for (int kk = 0; kk < 32; kk += 16) {
            // B fragments: n64 = 4 ldmatrix.x4 per split
            uint32_t bh[8][2], bl[8][2];
#pragma unroll
            for (int nb = 0; nb < 4; nb++) {
                int rown = n_base + nb * 16 + ((q >> 1) * 8) + lr;
                int colk = kk + (q & 1) * 8;
                uint32_t off = (uint32_t)(rown * RS + colk) * 2;
                uint32_t r4[4];
                ldmatrix_x4(r4, bBh + off);
                bh[nb * 2][0] = r4[0]; bh[nb * 2][1] = r4[1];
                bh[nb * 2 + 1][0] = r4[2]; bh[nb * 2 + 1][1] = r4[3];
                ldmatrix_x4(r4, bBl + off);
                bl[nb * 2][0] = r4[0]; bl[nb * 2][1] = r4[1];
                bl[nb * 2 + 1][0] = r4[2]; bl[nb * 2 + 1][1] = r4[3];
            }
#pragma unroll
            for (int mb = 0; mb < 2; mb++) {
                int rowm = m_base + mb * 16 + ((q & 1) * 8) + lr;
                int colk = kk + (q >> 1) * 8;
                uint32_t off = (uint32_t)(rowm * RS + colk) * 2;
                uint32_t ah[4], al[4];
                ldmatrix_x4(ah, bAh + off);
                ldmatrix_x4(al, bAl + off);
#pragma unroll
                for (int nb = 0; nb < 8; nb++) {
                    mma_bf16(acc[mb][nb], ah, bh[nb]);
                    mma_bf16(acc[mb][nb], ah, bl[nb]);
                    mma_bf16(acc[mb][nb], al, bh[nb]);
                }
            }
        }
        __syncthreads();
    }

    // epilogue: C fragment (row = lane>>2 [+8], col = (lane&3)*2 [+1])
#pragma unroll
    for (int mb = 0; mb < 2; mb++) {
        int row0 = m0 + m_base + mb * 16 + (lane >> 2);
#pragma unroll
        for (int nb = 0; nb < 8; nb++) {
            int col = n0 + n_base + nb * 8 + (lane & 3) * 2;
            float2 v0 = {acc[mb][nb][0], acc[mb][nb][1]};
            float2 v1 = {acc[mb][nb][2], acc[mb][nb][3]};
            *(float2*)(g_qv + (size_t)row0 * 2048 + col) = v0;
            *(float2*)(g_qv + (size_t)(row0 + 8) * 2048 + col) = v1;
        }
    }
#undef PREFETCH
}

// ---------------------------------------------------------------------------
// Fused attention (proven R2 kernel, vectorized O-phase)
// ---------------------------------------------------------------------------
__global__ void __launch_bounds__(256) k_attn(const float* __restrict__ x,
                                              const int* __restrict__ mask,
                                              const float* __restrict__ rr,
                                              float* __restrict__ out) {
    extern __shared__ float sm[];
    float* QrrT = sm;                 // [64 d][68]
    float* KT   = sm + 4352;          // [64 d][68]  (aliased by P[64 q][68])
    float* posT = sm + 8704;          // [64 d][132] (aliased by V[64 k][68])
    float* Es   = sm + 17152;         // 128
    float* msm  = sm + 17280;         // 64
    float* lsm  = sm + 17344;         // 64
    float* scsm = sm + 17408;         // 64
    float* mksm = sm + 17472;         // 64

    const int tid = threadIdx.x;
    const int bh = blockIdx.y;
    const int b = bh >> 4, h = bh & 15;
    const int q0 = blockIdx.x * 64;
    const int qg = tid >> 4, kg = tid & 15;

    {
        const float* qb = g_qv + (size_t)(b * SEQ + q0) * 2048 + h * 64;
#pragma unroll
        for (int r = 0; r < 4; r++) {
            int idx = tid + r * 256;
            int row = idx >> 4;
            int c4 = (idx & 15) * 4;
            float4 v = *(const float4*)(qb + (size_t)row * 2048 + c4);
            float4 bb = *(const float4*)(rr + h * 64 + c4);
            QrrT[(c4 + 0) * 68 + row] = v.x + bb.x;
            QrrT[(c4 + 1) * 68 + row] = v.y + bb.y;
            QrrT[(c4 + 2) * 68 + row] = v.z + bb.z;
            QrrT[(c4 + 3) * 68 + row] = v.w + bb.w;
        }
    }
    if (tid < 64) { msm[tid] = -1e30f; lsm[tid] = 0.f; }

    float o[4][4] = {};

    for (int k0 = 0; k0 < SEQ; k0 += 64) {
        const int base = 449 + k0 - q0;
        __syncthreads();

        {
            const float* kb = x + (size_t)(b * SEQ + k0) * DM + h * 64;
#pragma unroll
            for (int r = 0; r < 4; r++) {
                int idx = tid + r * 256;
                int row = idx >> 4;
                int c4 = (idx & 15) * 4;
                float4 v = *(const float4*)(kb + (size_t)row * DM + c4);
                KT[(c4 + 0) * 68 + row] = v.x;
                KT[(c4 + 1) * 68 + row] = v.y;
                KT[(c4 + 2) * 68 + row] = v.z;
                KT[(c4 + 3) * 68 + row] = v.w;
            }
        }
        {
#pragma unroll
            for (int r = 0; r < 8; r++) {
                int idx = tid + r * 256;
                int row = idx >> 4;
                int c4 = (idx & 15) * 4;
                if (row < 127) {
                    float4 v = *(const float4*)(g_pos + (size_t)(base + row) * 64 + c4);
                    posT[(c4 + 0) * 132 + row] = v.x;
                    posT[(c4 + 1) * 132 + row] = v.y;
                    posT[(c4 + 2) * 132 + row] = v.z;
                    posT[(c4 + 3) * 132 + row] = v.w;
                }
            }
        }
        if (tid < 128) Es[tid] = (tid < 127) ? g_E[h * 1024 + base + tid] : 0.f;
        if (tid < 64)  mksm[tid] = (float)mask[b * SEQ + k0 + tid];
        __syncthreads();

        // --- S = A1.K^T + A1.pos(shifted) ---
        float c[4][4] = {};
        const int w = 60 + 4 * (kg - qg);
#pragma unroll 2
        for (int d = 0; d < 64; d++) {
            float4 a4 = *(const float4*)(QrrT + d * 68 + qg * 4);
            float4 k4 = *(const float4*)(KT + d * 68 + kg * 4);
            float4 p0 = *(const float4*)(posT + d * 132 + w);
            float4 p1 = *(const float4*)(posT + d * 132 + w + 4);
            float av[4] = {a4.x, a4.y, a4.z, a4.w};
            float kv[4] = {k4.x, k4.y, k4.z, k4.w};
            float pv[8] = {p0.x, p0.y, p0.z, p0.w, p1.x, p1.y, p1.z, p1.w};
#pragma unroll
            for (int i = 0; i < 4; i++)
#pragma unroll
                for (int j = 0; j < 4; j++) {
                    c[i][j] += av[i] * kv[j];
                    c[i][j] += av[i] * pv[3 + j - i];
                }
        }
#pragma unroll
        for (int i = 0; i < 4; i++)
#pragma unroll
            for (int j = 0; j < 4; j++) {
                float cc = c[i][j] + Es[w + 3 + j - i];
                float mv = mksm[kg * 4 + j];
                c[i][j] = cc * mv - (1.f - mv) * 1e8f;
            }

        float rmax[4];
#pragma unroll
        for (int i = 0; i < 4; i++)
            rmax[i] = fmaxf(fmaxf(c[i][0], c[i][1]), fmaxf(c[i][2], c[i][3]));
#pragma unroll
        for (int off = 8; off >= 1; off >>= 1)
#pragma unroll
            for (int i = 0; i < 4; i++)
                rmax[i] = fmaxf(rmax[i], __shfl_xor_sync(0xffffffffu, rmax[i], off));
        float mold[4], mnew[4];
#pragma unroll
        for (int i = 0; i < 4; i++) {
            mold[i] = msm[qg * 4 + i];
            mnew[i] = fmaxf(mold[i], rmax[i]);
        }
        __syncthreads();

        float rsum[4] = {0.f, 0.f, 0.f, 0.f};
#pragma unroll
        for (int i = 0; i < 4; i++) {
            float4 pr;
            pr.x = __expf(c[i][0] - mnew[i]);
            pr.y = __expf(c[i][1] - mnew[i]);
            pr.z = __expf(c[i][2] - mnew[i]);
            pr.w = __expf(c[i][3] - mnew[i]);
            rsum[i] += pr.x + pr.y + pr.z + pr.w;
            *(float4*)(KT + (qg * 4 + i) * 68 + kg * 4) = pr;
        }
#pragma unroll
        for (int off = 8; off >= 1; off >>= 1)
#pragma unroll
            for (int i = 0; i < 4; i++)
                rsum[i] += __shfl_xor_sync(0xffffffffu, rsum[i], off);
        if (kg == 0) {
#pragma unroll
            for (int i = 0; i < 4; i++) {
                int q = qg * 4 + i;
                float s = __expf(mold[i] - mnew[i]);
                msm[q] = mnew[i];
                scsm[q] = s;
                lsm[q] = lsm[q] * s + rsum[i];
            }
        }
        {
            const float* vb = g_qv + (size_t)(b * SEQ + k0) * 2048 + 1024 + h * 64;
#pragma unroll
            for (int r = 0; r < 4; r++) {
                int idx = tid + r * 256;
                int row = idx >> 4;
                int c4 = (idx & 15) * 4;
                float4 v = *(const float4*)(vb + (size_t)row * 2048 + c4);
                *(float4*)(posT + row * 68 + c4) = v;
            }
        }
        __syncthreads();

        // --- O = O*scale + P @ V ---
#pragma unroll
        for (int i = 0; i < 4; i++) {
            float s = scsm[qg * 4 + i];
#pragma unroll
            for (int j = 0; j < 4; j++) o[i][j] *= s;
        }
#pragma unroll 4
        for (int kk = 0; kk < 64; kk += 4) {
            float4 pr[4], vr[4];
#pragma unroll
            for (int i = 0; i < 4; i++)
                pr[i] = *(const float4*)(KT + (qg * 4 + i) * 68 + kk);
#pragma unroll
            for (int j = 0; j < 4; j++)
                vr[j] = *(const float4*)(posT + (kk + j) * 68 + kg * 4);
            float P[4][4] = {{pr[0].x, pr[0].y, pr[0].z, pr[0].w},
                             {pr[1].x, pr[1].y, pr[1].z, pr[1].w},
                             {pr[2].x, pr[2].y, pr[2].z, pr[2].w},
                             {pr[3].x, pr[3].y, pr[3].z, pr[3].w}};
            float V[4][4] = {{vr[0].x, vr[0].y, vr[0].z, vr[0].w},
                             {vr[1].x, vr[1].y, vr[1].z, vr[1].w},
                             {vr[2].x, vr[2].y, vr[2].z, vr[2].w},
                             {vr[3].x, vr[3].y, vr[3].z, vr[3].w}};
#pragma unroll
            for (int i = 0; i < 4; i++)
#pragma unroll
                for (int j = 0; j < 4; j++) {
                    o[i][0] += P[i][j] * V[j][0];
                    o[i][1] += P[i][j] * V[j][1];
                    o[i][2] += P[i][j] * V[j][2];
                    o[i][3] += P[i][j] * V[j][3];
                }
        }
    }

#pragma unroll
    for (int i = 0; i < 4; i++) {
        int q = q0 + qg * 4 + i;
        float inv = 1.f / lsm[qg * 4 + i];
        float4 r;
        r.x = o[i][0] * inv;
        r.y = o[i][1] * inv;
        r.z = o[i][2] * inv;
        r.w = o[i][3] * inv;
        *(float4*)(out + ((size_t)(b * SEQ) + q) * DM + h * 64 + kg * 4) = r;
    }
}

// ---------------------------------------------------------------------------
extern "C" void kernel_launch(void* const* d_in, const int* in_sizes, int n_in,
                              void* d_out, int out_size) {
    const float* x   = (const float*)d_in[0];
    const int*   msk = (const int*)d_in[1];
    const float* Wqv = (const float*)d_in[2];
    const float* rr  = (const float*)d_in[3];
    const float* rw  = (const float*)d_in[4];
    float* out = (float*)d_out;

    cudaFuncSetAttribute(k_attn, cudaFuncAttributeMaxDynamicSharedMemorySize, 70144);
    cudaFuncSetAttribute(k_mm, cudaFuncAttributeMaxDynamicSharedMemorySize, 2 * STAGE_B);

    k_cvt_x<<<4096, 256>>>(x);
    k_cvt_w<<<dim3(64, 32), dim3(32, 8)>>>(Wqv);
    k_pos<<<256, 256>>>();
    k_E<<<dim3(4, 16), 256>>>(rr, rw);
    k_mm<<<dim3(16, 32), 256, 2 * STAGE_B>>>();
    k_attn<<<dim3(8, 128), 256, 70144>>>(x, msk, rr, out);
}

// round 8
// speedup vs baseline: 1.6440x; 1.2879x over previous
#include <cuda_runtime.h>
#include <cuda_bf16.h>
#include <math.h>
#include <cstdint>

#define NB 8
#define SEQ 512
#define DM 1024
#define NH 16
#define HDIM 64

// ---------------- scratch (static __device__: allocation-guard safe) -------
__device__ float g_pos[1024 * 64];            // relative positional table (fp32)
__device__ float g_E[16 * 1024];              // (r_w - r_r) . pos[j]
__device__ float g_qv[4096 * 2048];           // x @ Wqv (fp32)
__device__ __nv_bfloat16 g_xhi[4096 * 1024];  // x split hi (also K operand)
__device__ __nv_bfloat16 g_xlo[4096 * 1024];  // x split lo
__device__ __nv_bfloat16 g_whi[2048 * 1024];  // Wqv^T split hi  [n][k]
__device__ __nv_bfloat16 g_wlo[2048 * 1024];  // Wqv^T split lo
__device__ __nv_bfloat16 g_push[1024 * 64];   // pos split hi
__device__ __nv_bfloat16 g_posl[1024 * 64];   // pos split lo
__device__ __nv_bfloat16 g_vhi[4096 * 1024];  // V split hi
__device__ __nv_bfloat16 g_vlo[4096 * 1024];  // V split lo

// ---------------- helpers ---------------------------------------------------
__device__ __forceinline__ uint32_t smem_u32(const void* p) {
    uint32_t a;
    asm("{ .reg .u64 t; cvta.to.shared.u64 t, %1; cvt.u32.u64 %0, t; }" : "=r"(a) : "l"(p));
    return a;
}
__device__ __forceinline__ void ldmatrix_x4(uint32_t* r, uint32_t addr) {
    asm volatile("ldmatrix.sync.aligned.m8n8.x4.shared.b16 {%0,%1,%2,%3}, [%4];"
                 : "=r"(r[0]), "=r"(r[1]), "=r"(r[2]), "=r"(r[3]) : "r"(addr));
}
__device__ __forceinline__ void ldmatrix_x4_t(uint32_t* r, uint32_t addr) {
    asm volatile("ldmatrix.sync.aligned.m8n8.x4.trans.shared.b16 {%0,%1,%2,%3}, [%4];"
                 : "=r"(r[0]), "=r"(r[1]), "=r"(r[2]), "=r"(r[3]) : "r"(addr));
}
__device__ __forceinline__ void mma_bf16(float* c, const uint32_t* a, const uint32_t* b) {
    asm volatile("mma.sync.aligned.m16n8k16.row.col.f32.bf16.bf16.f32 "
                 "{%0,%1,%2,%3}, {%4,%5,%6,%7}, {%8,%9}, {%0,%1,%2,%3};"
                 : "+f"(c[0]), "+f"(c[1]), "+f"(c[2]), "+f"(c[3])
                 : "r"(a[0]), "r"(a[1]), "r"(a[2]), "r"(a[3]), "r"(b[0]), "r"(b[1]));
}
__device__ __forceinline__ void cp_async16(uint32_t saddr, const void* gaddr) {
    asm volatile("cp.async.cg.shared.global [%0], [%1], 16;" ::"r"(saddr), "l"(gaddr));
}
#define CP_COMMIT() asm volatile("cp.async.commit_group;" ::: "memory")
#define CP_WAIT(N) asm volatile("cp.async.wait_group %0;" ::"n"(N) : "memory")

__device__ __forceinline__ uint32_t pack2(__nv_bfloat16 lo, __nv_bfloat16 hi) {
    uint16_t a = *(uint16_t*)&lo, b = *(uint16_t*)&hi;
    return (uint32_t)a | ((uint32_t)b << 16);
}

// ---------------------------------------------------------------------------
// prep: bf16 hi/lo split of x
// ---------------------------------------------------------------------------
__global__ void k_cvt_x(const float* __restrict__ x) {
    int i = (blockIdx.x * blockDim.x + threadIdx.x) * 4;
    float4 v = *(const float4*)(x + i);
    float a[4] = {v.x, v.y, v.z, v.w};
    __nv_bfloat16 h[4], l[4];
#pragma unroll
    for (int j = 0; j < 4; j++) {
        h[j] = __float2bfloat16(a[j]);
        l[j] = __float2bfloat16(a[j] - __bfloat162float(h[j]));
    }
    *(uint2*)(g_xhi + i) = *(uint2*)h;
    *(uint2*)(g_xlo + i) = *(uint2*)l;
}

// prep: V half of g_qv -> bf16 hi/lo  (layout [b*S+s][1024])
__global__ void k_cvt_v() {
    int i = (blockIdx.x * blockDim.x + threadIdx.x) * 4;
    int row = i >> 10, c = i & 1023;
    float4 v = *(const float4*)(g_qv + (size_t)row * 2048 + 1024 + c);
    float a[4] = {v.x, v.y, v.z, v.w};
    __nv_bfloat16 h[4], l[4];
#pragma unroll
    for (int j = 0; j < 4; j++) {
        h[j] = __float2bfloat16(a[j]);
        l[j] = __float2bfloat16(a[j] - __bfloat162float(h[j]));
    }
    *(uint2*)(g_vhi + i) = *(uint2*)h;
    *(uint2*)(g_vlo + i) = *(uint2*)l;
}

// prep: Wqv^T with bf16 hi/lo split (tiled transpose)
__global__ void k_cvt_w(const float* __restrict__ W) {
    __shared__ float t[32][33];
    int tx = threadIdx.x, ty = threadIdx.y;
    int n0 = blockIdx.x * 32, k0 = blockIdx.y * 32;
#pragma unroll
    for (int i = 0; i < 4; i++)
        t[ty + i * 8][tx] = W[(size_t)(k0 + ty + i * 8) * 2048 + n0 + tx];
    __syncthreads();
#pragma unroll
    for (int i = 0; i < 4; i++) {
        int n = n0 + ty + i * 8;
        float v = t[tx][ty + i * 8];
        __nv_bfloat16 h = __float2bfloat16(v);
        g_whi[(size_t)n * 1024 + k0 + tx] = h;
        g_wlo[(size_t)n * 1024 + k0 + tx] = __float2bfloat16(v - __bfloat162float(h));
    }
}

// ---------------------------------------------------------------------------
// pos table (fp32 + bf16 splits) + E table
// ---------------------------------------------------------------------------
__global__ void k_pos() {
    int idx = blockIdx.x * blockDim.x + threadIdx.x;
    if (idx >= 1024 * 64) return;
    int j = idx >> 6;
    int i = idx & 63;
    const float C = -logf(10000.0f) / 31.0f;
    int ii = (i < 32) ? i : (i - 32);
    float freq = expf((float)ii * C);
    float arg = (float)(j - 512) * freq;
    float v = (i < 32) ? sinf(arg) : cosf(arg);
    g_pos[idx] = v;
    __nv_bfloat16 h = __float2bfloat16(v);
    g_push[idx] = h;
    g_posl[idx] = __float2bfloat16(v - __bfloat162float(h));
}

__global__ void k_E(const float* __restrict__ rr, const float* __restrict__ rw) {
    int j = blockIdx.x * blockDim.x + threadIdx.x;
    int h = blockIdx.y;
    float s = 0.f;
#pragma unroll 8
    for (int d = 0; d < 64; d++)
        s += (rw[h * 64 + d] - rr[h * 64 + d]) * g_pos[j * 64 + d];
    g_E[h * 1024 + j] = s;
}

// ---------------------------------------------------------------------------
// qv = x @ Wqv via mma.sync bf16 2-split (proven R6 kernel)
// ---------------------------------------------------------------------------
#define RS 72
#define TILE_B 18432
#define STAGE_B 73728

__global__ void __launch_bounds__(256) k_mm() {
    extern __shared__ __nv_bfloat16 smb[];
    const uint32_t sb = smem_u32(smb);
    const int tid = threadIdx.x;
    const int wid = tid >> 5, lane = tid & 31;
    const int m0 = blockIdx.y * 128, n0 = blockIdx.x * 128;

    const __nv_bfloat16* src0 = g_xhi + (size_t)m0 * 1024;
    const __nv_bfloat16* src1 = g_xlo + (size_t)m0 * 1024;
    const __nv_bfloat16* src2 = g_whi + (size_t)n0 * 1024;
    const __nv_bfloat16* src3 = g_wlo + (size_t)n0 * 1024;

    const int p_row = tid >> 1;
    const int p_c0 = (tid & 1) * 2;

    const int wm = wid >> 1, wn = wid & 1;
    const int m_base = wm * 32, n_base = wn * 64;
    const int lr = lane & 7, q = lane >> 3;

    float acc[2][8][4];
#pragma unroll
    for (int i = 0; i < 2; i++)
#pragma unroll
        for (int j = 0; j < 8; j++)
#pragma unroll
            for (int k = 0; k < 4; k++) acc[i][j][k] = 0.f;

#define PREFETCH(KT, STAGE)                                                              \
    do {                                                                                 \
        const int _k0 = (KT) * 32;                                                       \
        const uint32_t _stg = sb + (STAGE) * STAGE_B;                                    \
        const uint32_t _soff = (uint32_t)(p_row * RS) * 2 + p_c0 * 16;                   \
        const size_t _goff = (size_t)p_row * 1024 + _k0 + p_c0 * 8;                      \
        cp_async16(_stg + _soff, src0 + _goff);                                          \
        cp_async16(_stg + _soff + 16, src0 + _goff + 8);                                 \
        cp_async16(_stg + TILE_B + _soff, src1 + _goff);                                 \
        cp_async16(_stg + TILE_B + _soff + 16, src1 + _goff + 8);                        \
        cp_async16(_stg + 2 * TILE_B + _soff, src2 + _goff);                             \
        cp_async16(_stg + 2 * TILE_B + _soff + 16, src2 + _goff + 8);                    \
        cp_async16(_stg + 3 * TILE_B + _soff, src3 + _goff);                             \
        cp_async16(_stg + 3 * TILE_B + _soff + 16, src3 + _goff + 8);                    \
    } while (0)

    PREFETCH(0, 0);
    CP_COMMIT();

    for (int kt = 0; kt < 32; kt++) {
        const int stage = kt & 1;
        if (kt + 1 < 32) {
            PREFETCH(kt + 1, stage ^ 1);
            CP_COMMIT();
            CP_WAIT(1);
        } else {
            CP_WAIT(0);
        }
        __syncthreads();

        const uint32_t stg = sb + stage * STAGE_B;
        const uint32_t bAh = stg, bAl = stg + TILE_B;
        const uint32_t bBh = stg + 2 * TILE_B, bBl = stg + 3 * TILE_B;

#pragma unroll
        for (int kk = 0; kk < 32; kk += 16) {
            uint32_t bh[8][2], bl[8][2];
#pragma unroll
            for (int nb = 0; nb < 4; nb++) {
                int rown = n_base + nb * 16 + ((q >> 1) * 8) + lr;
                int colk = kk + (q & 1) * 8;
                uint32_t off = (uint32_t)(rown * RS + colk) * 2;
                uint32_t r4[4];
                ldmatrix_x4(r4, bBh + off);
                bh[nb * 2][0] = r4[0]; bh[nb * 2][1] = r4[1];
                bh[nb * 2 + 1][0] = r4[2]; bh[nb * 2 + 1][1] = r4[3];
                ldmatrix_x4(r4, bBl + off);
                bl[nb * 2][0] = r4[0]; bl[nb * 2][1] = r4[1];
                bl[nb * 2 + 1][0] = r4[2]; bl[nb * 2 + 1][1] = r4[3];
            }
#pragma unroll
            for (int mb = 0; mb < 2; mb++) {
                int rowm = m_base + mb * 16 + ((q & 1) * 8) + lr;
                int colk = kk + (q >> 1) * 8;
                uint32_t off = (uint32_t)(rowm * RS + colk) * 2;
                uint32_t ah[4], al[4];
                ldmatrix_x4(ah, bAh + off);
                ldmatrix_x4(al, bAl + off);
#pragma unroll
                for (int nb = 0; nb < 8; nb++) {
                    mma_bf16(acc[mb][nb], ah, bh[nb]);
                    mma_bf16(acc[mb][nb], ah, bl[nb]);
                    mma_bf16(acc[mb][nb], al, bh[nb]);
                }
            }
        }
        __syncthreads();
    }

#pragma unroll
    for (int mb = 0; mb < 2; mb++) {
        int row0 = m0 + m_base + mb * 16 + (lane >> 2);
#pragma unroll
        for (int nb = 0; nb < 8; nb++) {
            int col = n0 + n_base + nb * 8 + (lane & 3) * 2;
            float2 v0 = {acc[mb][nb][0], acc[mb][nb][1]};
            float2 v1 = {acc[mb][nb][2], acc[mb][nb][3]};
            *(float2*)(g_qv + (size_t)row0 * 2048 + col) = v0;
            *(float2*)(g_qv + (size_t)(row0 + 8) * 2048 + col) = v1;
        }
    }
#undef PREFETCH
}

// ---------------------------------------------------------------------------
// Tensor-core fused attention.
// CTA = (b,h) x 64-q tile, 4 warps (warp w owns q rows 16w..16w+15).
// Per k-tile (64 keys):
//   G  = A1 @ posWin^T (64x128) -> fp32 smem, gathered as BD[q,k]=G[q,k-q+63]
//   AC = A1 @ K^T (64x64) in regs; combine + mask + online softmax;
//   P -> bf16 hi/lo smem; O += P @ V (ldmatrix.trans for V).
// All contractions bf16 2-split (3 mma products) with fp32 accumulate.
// ---------------------------------------------------------------------------
#define SM_A1H 0
#define SM_A1L 9216
#define SM_KVH 18432
#define SM_KVL 27648
#define SM_POSH 36864
#define SM_POSL 55296
#define SM_GS 73728
#define SM_PH 73728
#define SM_PL 82944
#define SM_ES 107520
#define SM_MK 108032
#define SM_ATTN_TOT 108288

__global__ void __launch_bounds__(128) k_attn(const int* __restrict__ mask,
                                              const float* __restrict__ rr,
                                              float* __restrict__ out) {
    extern __shared__ char smc[];
    const uint32_t sb = smem_u32(smc);
    float* Gs = (float*)(smc + SM_GS);
    float* Es = (float*)(smc + SM_ES);
    float* mk = (float*)(smc + SM_MK);

    const int tid = threadIdx.x;
    const int wid = tid >> 5, lane = tid & 31;
    const int lr = lane & 7, qd = lane >> 3;
    const int bh = blockIdx.y;
    const int b = bh >> 4, h = bh & 15;
    const int q0 = blockIdx.x * 64;

    // ---- prologue: A1 = q + r_r, bf16 split into smem ----
    for (int i = tid; i < 1024; i += 128) {
        int row = i >> 4, f4 = i & 15;
        float4 v = *(const float4*)(g_qv + (size_t)(b * SEQ + q0 + row) * 2048 + h * 64 + f4 * 4);
        float4 bb = *(const float4*)(rr + h * 64 + f4 * 4);
        float s0 = v.x + bb.x, s1 = v.y + bb.y, s2 = v.z + bb.z, s3 = v.w + bb.w;
        __nv_bfloat16 h0 = __float2bfloat16(s0), h1 = __float2bfloat16(s1);
        __nv_bfloat16 h2 = __float2bfloat16(s2), h3 = __float2bfloat16(s3);
        __nv_bfloat16 l0 = __float2bfloat16(s0 - __bfloat162float(h0));
        __nv_bfloat16 l1 = __float2bfloat16(s1 - __bfloat162float(h1));
        __nv_bfloat16 l2 = __float2bfloat16(s2 - __bfloat162float(h2));
        __nv_bfloat16 l3 = __float2bfloat16(s3 - __bfloat162float(h3));
        uint2 ph = {pack2(h0, h1), pack2(h2, h3)};
        uint2 pl = {pack2(l0, l1), pack2(l2, l3)};
        *(uint2*)(smc + SM_A1H + (row * RS + f4 * 4) * 2) = ph;
        *(uint2*)(smc + SM_A1L + (row * RS + f4 * 4) * 2) = pl;
    }
    __syncthreads();

    // persistent A1 fragments
    uint32_t a1h[4][4], a1l[4][4];
    {
        int rowA = 16 * wid + (qd & 1) * 8 + lr;
#pragma unroll
        for (int ks = 0; ks < 4; ks++) {
            int colA = ks * 16 + (qd >> 1) * 8;
            ldmatrix_x4(a1h[ks], sb + SM_A1H + (uint32_t)(rowA * RS + colA) * 2);
            ldmatrix_x4(a1l[ks], sb + SM_A1L + (uint32_t)(rowA * RS + colA) * 2);
        }
    }

    float m0 = -1e30f, m1 = -1e30f, l0 = 0.f, l1 = 0.f;
    float O[8][4];
#pragma unroll
    for (int i = 0; i < 8; i++)
#pragma unroll
        for (int j = 0; j < 4; j++) O[i][j] = 0.f;

    const int rq0 = 16 * wid + (lane >> 2);   // local q row (e0,e1)
    const int rq1 = rq0 + 8;                  // local q row (e2,e3)

    for (int kt = 0; kt < 8; kt++) {
        const int k0 = kt * 64;
        const int base = 449 + k0 - q0;
        __syncthreads();   // prior-iter P/V/pos/Es consumers done

        // ---- stage K splits (64x64) ----
        for (int i = tid; i < 512; i += 128) {
            int row = i >> 3, c = i & 7;
            size_t g = (size_t)(b * SEQ + k0 + row) * 1024 + h * 64 + c * 8;
            *(uint4*)(smc + SM_KVH + (row * RS + c * 8) * 2) = *(const uint4*)(g_xhi + g);
            *(uint4*)(smc + SM_KVL + (row * RS + c * 8) * 2) = *(const uint4*)(g_xlo + g);
        }
        // ---- stage pos window splits (128x64), clamped ----
        for (int i = tid; i < 1024; i += 128) {
            int row = i >> 3, c = i & 7;
            int j = base + row; if (j > 1023) j = 1023;
            size_t g = (size_t)j * 64 + c * 8;
            *(uint4*)(smc + SM_POSH + (row * RS + c * 8) * 2) = *(const uint4*)(g_push + g);
            *(uint4*)(smc + SM_POSL + (row * RS + c * 8) * 2) = *(const uint4*)(g_posl + g);
        }
        if (tid < 128) { int j = base + tid; if (j > 1023) j = 1023; Es[tid] = g_E[h * 1024 + j]; }
        if (tid < 64) mk[tid] = (float)mask[b * SEQ + k0 + tid];
        __syncthreads();

        // ---- G = A1 @ posWin^T (64x128) -> Gs ----
        {
            int rowBg = (qd >> 1) * 8 + lr;
            int rg = 16 * wid + (lane >> 2);
            int cgl = (lane & 3) * 2;
#pragma unroll
            for (int nb = 0; nb < 8; nb++) {
                float g0[4] = {0.f, 0.f, 0.f, 0.f}, g1[4] = {0.f, 0.f, 0.f, 0.f};
#pragma unroll
                for (int ks = 0; ks < 4; ks++) {
                    int colB = ks * 16 + (qd & 1) * 8;
                    uint32_t off = (uint32_t)((nb * 16 + rowBg) * RS + colB) * 2;
                    uint32_t bh4[4], bl4[4];
                    ldmatrix_x4(bh4, sb + SM_POSH + off);
                    ldmatrix_x4(bl4, sb + SM_POSL + off);
                    mma_bf16(g0, a1h[ks], bh4);
                    mma_bf16(g0, a1h[ks], bl4);
                    mma_bf16(g0, a1l[ks], bh4);
                    mma_bf16(g1, a1h[ks], bh4 + 2);
                    mma_bf16(g1, a1h[ks], bl4 + 2);
                    mma_bf16(g1, a1l[ks], bh4 + 2);
                }
                int cg = nb * 16 + cgl;
                *(float2*)&Gs[rg * 132 + cg] = make_float2(g0[0], g0[1]);
                *(float2*)&Gs[(rg + 8) * 132 + cg] = make_float2(g0[2], g0[3]);
                *(float2*)&Gs[rg * 132 + cg + 8] = make_float2(g1[0], g1[1]);
                *(float2*)&Gs[(rg + 8) * 132 + cg + 8] = make_float2(g1[2], g1[3]);
            }
        }

        // ---- AC = A1 @ K^T (64x64) in regs ----
        float acc[8][4];
#pragma unroll
        for (int i = 0; i < 8; i++)
#pragma unroll
            for (int j = 0; j < 4; j++) acc[i][j] = 0.f;
        {
            int rowBg = (qd >> 1) * 8 + lr;
#pragma unroll
            for (int nb = 0; nb < 4; nb++) {
#pragma unroll
                for (int ks = 0; ks < 4; ks++) {
                    int colB = ks * 16 + (qd & 1) * 8;
                    uint32_t off = (uint32_t)((nb * 16 + rowBg) * RS + colB) * 2;
                    uint32_t kh4[4], kl4[4];
                    ldmatrix_x4(kh4, sb + SM_KVH + off);
                    ldmatrix_x4(kl4, sb + SM_KVL + off);
                    mma_bf16(acc[nb * 2], a1h[ks], kh4);
                    mma_bf16(acc[nb * 2], a1h[ks], kl4);
                    mma_bf16(acc[nb * 2], a1l[ks], kh4);
                    mma_bf16(acc[nb * 2 + 1], a1h[ks], kh4 + 2);
                    mma_bf16(acc[nb * 2 + 1], a1h[ks], kl4 + 2);
                    mma_bf16(acc[nb * 2 + 1], a1l[ks], kh4 + 2);
                }
            }
        }
        __syncthreads();   // Gs complete

        // ---- combine: S = AC + gather(G) + E, mask ----
        float rmax0 = -1e30f, rmax1 = -1e30f;
#pragma unroll
        for (int nt = 0; nt < 8; nt++) {
            int c0 = nt * 8 + (lane & 3) * 2;
#pragma unroll
            for (int e = 0; e < 4; e++) {
                int q = (e < 2) ? rq0 : rq1;
                int k = c0 + (e & 1);
                int jj = k - q + 63;
                float s = acc[nt][e] + Gs[q * 132 + jj] + Es[jj];
                float mv = mk[k];
                s = s * mv - (1.f - mv) * 1e8f;
                acc[nt][e] = s;
                if (e < 2) rmax0 = fmaxf(rmax0, s); else rmax1 = fmaxf(rmax1, s);
            }
        }
        rmax0 = fmaxf(rmax0, __shfl_xor_sync(0xffffffffu, rmax0, 1));
        rmax0 = fmaxf(rmax0, __shfl_xor_sync(0xffffffffu, rmax0, 2));
        rmax1 = fmaxf(rmax1, __shfl_xor_sync(0xffffffffu, rmax1, 1));
        rmax1 = fmaxf(rmax1, __shfl_xor_sync(0xffffffffu, rmax1, 2));
        float mn0 = fmaxf(m0, rmax0), mn1 = fmaxf(m1, rmax1);
        float sc0 = __expf(m0 - mn0), sc1 = __expf(m1 - mn1);
        m0 = mn0; m1 = mn1;
        float rs0 = 0.f, rs1 = 0.f;
#pragma unroll
        for (int nt = 0; nt < 8; nt++) {
#pragma unroll
            for (int e = 0; e < 4; e++) {
                float p = __expf(acc[nt][e] - ((e < 2) ? mn0 : mn1));
                acc[nt][e] = p;
                if (e < 2) rs0 += p; else rs1 += p;
            }
        }
        rs0 += __shfl_xor_sync(0xffffffffu, rs0, 1);
        rs0 += __shfl_xor_sync(0xffffffffu, rs0, 2);
        rs1 += __shfl_xor_sync(0xffffffffu, rs1, 1);
        rs1 += __shfl_xor_sync(0xffffffffu, rs1, 2);
        l0 = l0 * sc0 + rs0;
        l1 = l1 * sc1 + rs1;
#pragma unroll
        for (int nt = 0; nt < 8; nt++) {
            O[nt][0] *= sc0; O[nt][1] *= sc0;
            O[nt][2] *= sc1; O[nt][3] *= sc1;
        }
        __syncthreads();   // all warps done reading Gs

        // ---- P splits into smem (over Gs region) ----
#pragma unroll
        for (int nt = 0; nt < 8; nt++) {
            int c0 = nt * 8 + (lane & 3) * 2;
            __nv_bfloat16 h0 = __float2bfloat16(acc[nt][0]);
            __nv_bfloat16 h1 = __float2bfloat16(acc[nt][1]);
            __nv_bfloat16 h2 = __float2bfloat16(acc[nt][2]);
            __nv_bfloat16 h3 = __float2bfloat16(acc[nt][3]);
            __nv_bfloat16 e0 = __float2bfloat16(acc[nt][0] - __bfloat162float(h0));
            __nv_bfloat16 e1 = __float2bfloat16(acc[nt][1] - __bfloat162float(h1));
            __nv_bfloat16 e2 = __float2bfloat16(acc[nt][2] - __bfloat162float(h2));
            __nv_bfloat16 e3 = __float2bfloat16(acc[nt][3] - __bfloat162float(h3));
            *(uint32_t*)(smc + SM_PH + (rq0 * RS + c0) * 2) = pack2(h0, h1);
            *(uint32_t*)(smc + SM_PH + (rq1 * RS + c0) * 2) = pack2(h2, h3);
            *(uint32_t*)(smc + SM_PL + (rq0 * RS + c0) * 2) = pack2(e0, e1);
            *(uint32_t*)(smc + SM_PL + (rq1 * RS + c0) * 2) = pack2(e2, e3);
        }
        // ---- stage V splits into KV region ----
        for (int i = tid; i < 512; i += 128) {
            int row = i >> 3, c = i & 7;
            size_t g = (size_t)(b * SEQ + k0 + row) * 1024 + h * 64 + c * 8;
            *(uint4*)(smc + SM_KVH + (row * RS + c * 8) * 2) = *(const uint4*)(g_vhi + g);
            *(uint4*)(smc + SM_KVL + (row * RS + c * 8) * 2) = *(const uint4*)(g_vlo + g);
        }
        __syncthreads();

        // ---- O += P @ V ----
        {
            int rowP = 16 * wid + (qd & 1) * 8 + lr;
#pragma unroll
            for (int ks = 0; ks < 4; ks++) {
                int colP = ks * 16 + (qd >> 1) * 8;
                uint32_t ap[4], al[4];
                ldmatrix_x4(ap, sb + SM_PH + (uint32_t)(rowP * RS + colP) * 2);
                ldmatrix_x4(al, sb + SM_PL + (uint32_t)(rowP * RS + colP) * 2);
                int rowV = ks * 16 + (qd & 1) * 8 + lr;
#pragma unroll
                for (int dt = 0; dt < 4; dt++) {
                    int colV = dt * 16 + (qd >> 1) * 8;
                    uint32_t off = (uint32_t)(rowV * RS + colV) * 2;
                    uint32_t vh[4], vl[4];
                    ldmatrix_x4_t(vh, sb + SM_KVH + off);
                    ldmatrix_x4_t(vl, sb + SM_KVL + off);
                    mma_bf16(O[dt * 2], ap, vh);
                    mma_bf16(O[dt * 2], ap, vl);
                    mma_bf16(O[dt * 2], al, vh);
                    mma_bf16(O[dt * 2 + 1], ap, vh + 2);
                    mma_bf16(O[dt * 2 + 1], ap, vl + 2);
                    mma_bf16(O[dt * 2 + 1], al, vh + 2);
                }
            }
        }
    }

    // ---- epilogue: out = O / l ----
    float li0 = 1.f / l0, li1 = 1.f / l1;
#pragma unroll
    for (int nt = 0; nt < 8; nt++) {
        int col = h * 64 + nt * 8 + (lane & 3) * 2;
        size_t r0o = (size_t)(b * SEQ + q0 + rq0) * DM + col;
        size_t r1o = (size_t)(b * SEQ + q0 + rq1) * DM + col;
        *(float2*)(out + r0o) = make_float2(O[nt][0] * li0, O[nt][1] * li0);
        *(float2*)(out + r1o) = make_float2(O[nt][2] * li1, O[nt][3] * li1);
    }
}

// ---------------------------------------------------------------------------
extern "C" void kernel_launch(void* const* d_in, const int* in_sizes, int n_in,
                              void* d_out, int out_size) {
    const float* x   = (const float*)d_in[0];
    const int*   msk = (const int*)d_in[1];
    const float* Wqv = (const float*)d_in[2];
    const float* rr  = (const float*)d_in[3];
    const float* rw  = (const float*)d_in[4];
    float* out = (float*)d_out;

    cudaFuncSetAttribute(k_attn, cudaFuncAttributeMaxDynamicSharedMemorySize, SM_ATTN_TOT);
    cudaFuncSetAttribute(k_mm, cudaFuncAttributeMaxDynamicSharedMemorySize, 2 * STAGE_B);

    k_cvt_x<<<4096, 256>>>(x);
    k_cvt_w<<<dim3(64, 32), dim3(32, 8)>>>(Wqv);
    k_pos<<<256, 256>>>();
    k_E<<<dim3(4, 16), 256>>>(rr, rw);
    k_mm<<<dim3(16, 32), 256, 2 * STAGE_B>>>();
    k_cvt_v<<<4096, 256>>>();
    k_attn<<<dim3(8, 128), 128, SM_ATTN_TOT>>>(msk, rr, out);
}

// round 10
// speedup vs baseline: 1.6823x; 1.0233x over previous
#include <cuda_runtime.h>
#include <cuda_bf16.h>
#include <math.h>
#include <cstdint>

#define NB 8
#define SEQ 512
#define DM 1024
#define NH 16
#define HDIM 64

// ---------------- scratch (static __device__: allocation-guard safe) -------
__device__ float g_pos[1024 * 64];            // relative positional table (fp32)
__device__ float g_E[16 * 1024];              // (r_w - r_r) . pos[j]
__device__ __nv_bfloat16 g_xhi[4096 * 1024];  // x split hi (K operand)
__device__ __nv_bfloat16 g_xlo[4096 * 1024];  // x split lo
__device__ __nv_bfloat16 g_whi[2048 * 1024];  // Wqv^T split hi  [n][k]
__device__ __nv_bfloat16 g_wlo[2048 * 1024];  // Wqv^T split lo
__device__ __nv_bfloat16 g_push[1024 * 64];   // pos split hi
__device__ __nv_bfloat16 g_posl[1024 * 64];   // pos split lo
__device__ __nv_bfloat16 g_qhi[4096 * 1024];  // A1 = q + r_r split hi
__device__ __nv_bfloat16 g_qlo[4096 * 1024];  // A1 split lo
__device__ __nv_bfloat16 g_vhi[4096 * 1024];  // V split hi
__device__ __nv_bfloat16 g_vlo[4096 * 1024];  // V split lo

// ---------------- helpers ---------------------------------------------------
__device__ __forceinline__ uint32_t smem_u32(const void* p) {
    uint32_t a;
    asm("{ .reg .u64 t; cvta.to.shared.u64 t, %1; cvt.u32.u64 %0, t; }" : "=r"(a) : "l"(p));
    return a;
}
__device__ __forceinline__ void ldmatrix_x4(uint32_t* r, uint32_t addr) {
    asm volatile("ldmatrix.sync.aligned.m8n8.x4.shared.b16 {%0,%1,%2,%3}, [%4];"
                 : "=r"(r[0]), "=r"(r[1]), "=r"(r[2]), "=r"(r[3]) : "r"(addr));
}
__device__ __forceinline__ void ldmatrix_x4_t(uint32_t* r, uint32_t addr) {
    asm volatile("ldmatrix.sync.aligned.m8n8.x4.trans.shared.b16 {%0,%1,%2,%3}, [%4];"
                 : "=r"(r[0]), "=r"(r[1]), "=r"(r[2]), "=r"(r[3]) : "r"(addr));
}
__device__ __forceinline__ void mma_bf16(float* c, const uint32_t* a, const uint32_t* b) {
    asm volatile("mma.sync.aligned.m16n8k16.row.col.f32.bf16.bf16.f32 "
                 "{%0,%1,%2,%3}, {%4,%5,%6,%7}, {%8,%9}, {%0,%1,%2,%3};"
                 : "+f"(c[0]), "+f"(c[1]), "+f"(c[2]), "+f"(c[3])
                 : "r"(a[0]), "r"(a[1]), "r"(a[2]), "r"(a[3]), "r"(b[0]), "r"(b[1]));
}
__device__ __forceinline__ void cp_async16(uint32_t saddr, const void* gaddr) {
    asm volatile("cp.async.cg.shared.global [%0], [%1], 16;" ::"r"(saddr), "l"(gaddr));
}
#define CP_COMMIT() asm volatile("cp.async.commit_group;" ::: "memory")
#define CP_WAIT(N) asm volatile("cp.async.wait_group %0;" ::"n"(N) : "memory")

__device__ __forceinline__ uint32_t pack2(__nv_bfloat16 lo, __nv_bfloat16 hi) {
    uint16_t a = *(uint16_t*)&lo, b = *(uint16_t*)&hi;
    return (uint32_t)a | ((uint32_t)b << 16);
}
__device__ __forceinline__ void store_split(__nv_bfloat16* hi, __nv_bfloat16* lo,
                                            size_t idx, float a, float b) {
    __nv_bfloat16 ha = __float2bfloat16(a), hb = __float2bfloat16(b);
    __nv_bfloat16 la = __float2bfloat16(a - __bfloat162float(ha));
    __nv_bfloat16 lb = __float2bfloat16(b - __bfloat162float(hb));
    *(uint32_t*)(hi + idx) = pack2(ha, hb);
    *(uint32_t*)(lo + idx) = pack2(la, lb);
}

// ---------------------------------------------------------------------------
// prep: bf16 hi/lo split of x
// ---------------------------------------------------------------------------
__global__ void k_cvt_x(const float* __restrict__ x) {
    int i = (blockIdx.x * blockDim.x + threadIdx.x) * 4;
    float4 v = *(const float4*)(x + i);
    float a[4] = {v.x, v.y, v.z, v.w};
    __nv_bfloat16 h[4], l[4];
#pragma unroll
    for (int j = 0; j < 4; j++) {
        h[j] = __float2bfloat16(a[j]);
        l[j] = __float2bfloat16(a[j] - __bfloat162float(h[j]));
    }
    *(uint2*)(g_xhi + i) = *(uint2*)h;
    *(uint2*)(g_xlo + i) = *(uint2*)l;
}

// prep: Wqv^T with bf16 hi/lo split (tiled transpose)
__global__ void k_cvt_w(const float* __restrict__ W) {
    __shared__ float t[32][33];
    int tx = threadIdx.x, ty = threadIdx.y;
    int n0 = blockIdx.x * 32, k0 = blockIdx.y * 32;
#pragma unroll
    for (int i = 0; i < 4; i++)
        t[ty + i * 8][tx] = W[(size_t)(k0 + ty + i * 8) * 2048 + n0 + tx];
    __syncthreads();
#pragma unroll
    for (int i = 0; i < 4; i++) {
        int n = n0 + ty + i * 8;
        float v = t[tx][ty + i * 8];
        __nv_bfloat16 h = __float2bfloat16(v);
        g_whi[(size_t)n * 1024 + k0 + tx] = h;
        g_wlo[(size_t)n * 1024 + k0 + tx] = __float2bfloat16(v - __bfloat162float(h));
    }
}

// ---------------------------------------------------------------------------
// pos table (fp32 + bf16 splits) + E table
// ---------------------------------------------------------------------------
__global__ void k_pos() {
    int idx = blockIdx.x * blockDim.x + threadIdx.x;
    if (idx >= 1024 * 64) return;
    int j = idx >> 6;
    int i = idx & 63;
    const float C = -logf(10000.0f) / 31.0f;
    int ii = (i < 32) ? i : (i - 32);
    float freq = expf((float)ii * C);
    float arg = (float)(j - 512) * freq;
    float v = (i < 32) ? sinf(arg) : cosf(arg);
    g_pos[idx] = v;
    __nv_bfloat16 h = __float2bfloat16(v);
    g_push[idx] = h;
    g_posl[idx] = __float2bfloat16(v - __bfloat162float(h));
}

__global__ void k_E(const float* __restrict__ rr, const float* __restrict__ rw) {
    int j = blockIdx.x * 128 + threadIdx.x;   // grid.x = 8
    int h = blockIdx.y;
    const float4* pp = (const float4*)(g_pos + (size_t)j * 64);
    const float4* pr = (const float4*)(rr + h * 64);
    const float4* pw = (const float4*)(rw + h * 64);
    float s = 0.f;
#pragma unroll
    for (int d = 0; d < 16; d++) {
        float4 p = pp[d], a = pw[d], bq = pr[d];
        s += (a.x - bq.x) * p.x + (a.y - bq.y) * p.y +
             (a.z - bq.z) * p.z + (a.w - bq.w) * p.w;
    }
    g_E[h * 1024 + j] = s;
}

// ---------------------------------------------------------------------------
// qv = x @ Wqv via mma.sync bf16 2-split; 3-stage cp.async pipeline.
// Epilogue writes A1=q+rr and V directly as bf16 hi/lo splits.
// ---------------------------------------------------------------------------
#define RS 72
#define TILE_B 18432
#define STAGE_B 73728

__global__ void __launch_bounds__(256) k_mm(const float* __restrict__ rr) {
    extern __shared__ __nv_bfloat16 smb[];
    const uint32_t sb = smem_u32(smb);
    const int tid = threadIdx.x;
    const int wid = tid >> 5, lane = tid & 31;
    const int m0 = blockIdx.y * 128, n0 = blockIdx.x * 128;

    const __nv_bfloat16* src0 = g_xhi + (size_t)m0 * 1024;
    const __nv_bfloat16* src1 = g_xlo + (size_t)m0 * 1024;
    const __nv_bfloat16* src2 = g_whi + (size_t)n0 * 1024;
    const __nv_bfloat16* src3 = g_wlo + (size_t)n0 * 1024;

    const int p_row = tid >> 1;
    const int p_c0 = (tid & 1) * 2;

    const int wm = wid >> 1, wn = wid & 1;
    const int m_base = wm * 32, n_base = wn * 64;
    const int lr = lane & 7, q = lane >> 3;

    float acc[2][8][4];
#pragma unroll
    for (int i = 0; i < 2; i++)
#pragma unroll
        for (int j = 0; j < 8; j++)
#pragma unroll
            for (int k = 0; k < 4; k++) acc[i][j][k] = 0.f;

#define PREFETCH(KT, STAGE)                                                              \
    do {                                                                                 \
        const int _k0 = (KT) * 32;                                                       \
        const uint32_t _stg = sb + (STAGE) * STAGE_B;                                    \
        const uint32_t _soff = (uint32_t)(p_row * RS) * 2 + p_c0 * 16;                   \
        const size_t _goff = (size_t)p_row * 1024 + _k0 + p_c0 * 8;                      \
        cp_async16(_stg + _soff, src0 + _goff);                                          \
        cp_async16(_stg + _soff + 16, src0 + _goff + 8);                                 \
        cp_async16(_stg + TILE_B + _soff, src1 + _goff);                                 \
        cp_async16(_stg + TILE_B + _soff + 16, src1 + _goff + 8);                        \
        cp_async16(_stg + 2 * TILE_B + _soff, src2 + _goff);                             \
        cp_async16(_stg + 2 * TILE_B + _soff + 16, src2 + _goff + 8);                    \
        cp_async16(_stg + 3 * TILE_B + _soff, src3 + _goff);                             \
        cp_async16(_stg + 3 * TILE_B + _soff + 16, src3 + _goff + 8);                    \
    } while (0)

    PREFETCH(0, 0);
    CP_COMMIT();
    PREFETCH(1, 1);
    CP_COMMIT();

    for (int kt = 0; kt < 32; kt++) {
        if (kt + 2 < 32) {
            const int st2 = (kt + 2) % 3;
            PREFETCH(kt + 2, st2);
        }
        CP_COMMIT();
        CP_WAIT(2);
        __syncthreads();

        const uint32_t stg = sb + (kt % 3) * STAGE_B;
        const uint32_t bAh = stg, bAl = stg + TILE_B;
        const uint32_t bBh = stg + 2 * TILE_B, bBl = stg + 3 * TILE_B;

#pragma unroll
        for (int kk = 0; kk < 32; kk += 16) {
            uint32_t bh[8][2], bl[8][2];
#pragma unroll
            for (int nb = 0; nb < 4; nb++) {
                int rown = n_base + nb * 16 + ((q >> 1) * 8) + lr;
                int colk = kk + (q & 1) * 8;
                uint32_t off = (uint32_t)(rown * RS + colk) * 2;
                uint32_t r4[4];
                ldmatrix_x4(r4, bBh + off);
                bh[nb * 2][0] = r4[0]; bh[nb * 2][1] = r4[1];
                bh[nb * 2 + 1][0] = r4[2]; bh[nb * 2 + 1][1] = r4[3];
                ldmatrix_x4(r4, bBl + off);
                bl[nb * 2][0] = r4[0]; bl[nb * 2][1] = r4[1];
                bl[nb * 2 + 1][0] = r4[2]; bl[nb * 2 + 1][1] = r4[3];
            }
#pragma unroll
            for (int mb = 0; mb < 2; mb++) {
                int rowm = m_base + mb * 16 + ((q & 1) * 8) + lr;
                int colk = kk + (q >> 1) * 8;
                uint32_t off = (uint32_t)(rowm * RS + colk) * 2;
                uint32_t ah[4], al[4];
                ldmatrix_x4(ah, bAh + off);
                ldmatrix_x4(al, bAl + off);
#pragma unroll
                for (int nb = 0; nb < 8; nb++) {
                    mma_bf16(acc[mb][nb], ah, bh[nb]);
                    mma_bf16(acc[mb][nb], ah, bl[nb]);
                    mma_bf16(acc[mb][nb], al, bh[nb]);
                }
            }
        }
        __syncthreads();
    }

    // epilogue: fused rr-add + bf16 hi/lo split to g_qhi/qlo or g_vhi/vlo
#pragma unroll
    for (int mb = 0; mb < 2; mb++) {
        int row0 = m0 + m_base + mb * 16 + (lane >> 2);
#pragma unroll
        for (int nb = 0; nb < 8; nb++) {
            int col = n0 + n_base + nb * 8 + (lane & 3) * 2;
            if (col < 1024) {
                float2 rb = *(const float2*)(rr + col);
                store_split(g_qhi, g_qlo, (size_t)row0 * 1024 + col,
                            acc[mb][nb][0] + rb.x, acc[mb][nb][1] + rb.y);
                store_split(g_qhi, g_qlo, (size_t)(row0 + 8) * 1024 + col,
                            acc[mb][nb][2] + rb.x, acc[mb][nb][3] + rb.y);
            } else {
                int c2 = col - 1024;
                store_split(g_vhi, g_vlo, (size_t)row0 * 1024 + c2,
                            acc[mb][nb][0], acc[mb][nb][1]);
                store_split(g_vhi, g_vlo, (size_t)(row0 + 8) * 1024 + c2,
                            acc[mb][nb][2], acc[mb][nb][3]);
            }
        }
    }
#undef PREFETCH
}

// ---------------------------------------------------------------------------
// Tensor-core fused attention with sliding-window G ring.
// G block b (64 pos cols, g in [64b, 64b+63]) lives in ring slot b&1.
// Tile kt gathers from blocks kt, kt+1; at end of tile kt (kt<7) computes
// block kt+2 (blocks 2..8; prologue does 0,1).
// Smem: K/V [0,18432) | pos [18432,36864) | Gs[64][2][68] fp32 [36864,71680)
//       P hi/lo (alias A1 staging) [71680,90112) | Es 512B | mk 256B
// ---------------------------------------------------------------------------
#define SM_KH 0
#define SM_KL 9216
#define SM_POSH 18432
#define SM_POSL 27648
#define SM_GS 36864
#define SM_PH 71680
#define SM_PL 80896
#define SM_ES 90112
#define SM_MK 90624
#define SM_ATTN_TOT 90880

__device__ __forceinline__ void g_block(uint32_t sb, float* Gs,
                                        const uint32_t (&a1h)[4][4],
                                        const uint32_t (&a1l)[4][4],
                                        int wid, int lane, int slot) {
    const int lr = lane & 7, qd = lane >> 3;
    const int rowBg = (qd >> 1) * 8 + lr;
    const int rg = 16 * wid + (lane >> 2);
    const int cgl = (lane & 3) * 2;
#pragma unroll
    for (int nb = 0; nb < 4; nb++) {
        float g0[4] = {0.f, 0.f, 0.f, 0.f}, g1[4] = {0.f, 0.f, 0.f, 0.f};
#pragma unroll
        for (int ks = 0; ks < 4; ks++) {
            int colB = ks * 16 + (qd & 1) * 8;
            uint32_t off = (uint32_t)((nb * 16 + rowBg) * RS + colB) * 2;
            uint32_t bh4[4], bl4[4];
            ldmatrix_x4(bh4, sb + SM_POSH + off);
            ldmatrix_x4(bl4, sb + SM_POSL + off);
            mma_bf16(g0, a1h[ks], bh4);
            mma_bf16(g0, a1h[ks], bl4);
            mma_bf16(g0, a1l[ks], bh4);
            mma_bf16(g1, a1h[ks], bh4 + 2);
            mma_bf16(g1, a1h[ks], bl4 + 2);
            mma_bf16(g1, a1l[ks], bh4 + 2);
        }
        int cg = nb * 16 + cgl;
        int bq = rg * 136 + slot * 68;
        *(float2*)&Gs[bq + cg] = make_float2(g0[0], g0[1]);
        *(float2*)&Gs[bq + 8 * 136 + cg] = make_float2(g0[2], g0[3]);
        *(float2*)&Gs[bq + cg + 8] = make_float2(g1[0], g1[1]);
        *(float2*)&Gs[bq + 8 * 136 + cg + 8] = make_float2(g1[2], g1[3]);
    }
}

__global__ void __launch_bounds__(128) k_attn(const int* __restrict__ mask,
                                              float* __restrict__ out) {
    extern __shared__ char smc[];
    const uint32_t sb = smem_u32(smc);
    float* Gs = (float*)(smc + SM_GS);
    float* Es = (float*)(smc + SM_ES);
    float* mk = (float*)(smc + SM_MK);

    const int tid = threadIdx.x;
    const int wid = tid >> 5, lane = tid & 31;
    const int lr = lane & 7, qd = lane >> 3;
    const int bh = blockIdx.y;
    const int b = bh >> 4, h = bh & 15;
    const int q0 = blockIdx.x * 64;
    const int base0 = 449 - q0;   // pos index of G global column 0

    // ---- prologue: stage A1 splits (into P alias region) ----
    for (int i = tid; i < 512; i += 128) {
        int row = i >> 3, c = i & 7;
        size_t g = (size_t)(b * SEQ + q0 + row) * 1024 + h * 64 + c * 8;
        *(uint4*)(smc + SM_PH + (row * RS + c * 8) * 2) = *(const uint4*)(g_qhi + g);
        *(uint4*)(smc + SM_PL + (row * RS + c * 8) * 2) = *(const uint4*)(g_qlo + g);
    }
    __syncthreads();

    uint32_t a1h[4][4], a1l[4][4];
    {
        int rowA = 16 * wid + (qd & 1) * 8 + lr;
#pragma unroll
        for (int ks = 0; ks < 4; ks++) {
            int colA = ks * 16 + (qd >> 1) * 8;
            ldmatrix_x4(a1h[ks], sb + SM_PH + (uint32_t)(rowA * RS + colA) * 2);
            ldmatrix_x4(a1l[ks], sb + SM_PL + (uint32_t)(rowA * RS + colA) * 2);
        }
    }

    // ---- prologue: G blocks 0 and 1 ----
#pragma unroll
    for (int bi = 0; bi < 2; bi++) {
        int pbase = base0 + 64 * bi;
        for (int i = tid; i < 512; i += 128) {
            int row = i >> 3, c = i & 7;
            int j = pbase + row; if (j > 1023) j = 1023;
            size_t g = (size_t)j * 64 + c * 8;
            *(uint4*)(smc + SM_POSH + (row * RS + c * 8) * 2) = *(const uint4*)(g_push + g);
            *(uint4*)(smc + SM_POSL + (row * RS + c * 8) * 2) = *(const uint4*)(g_posl + g);
        }
        __syncthreads();
        g_block(sb, Gs, a1h, a1l, wid, lane, bi);
        __syncthreads();
    }

    float m0 = -1e30f, m1 = -1e30f, l0 = 0.f, l1 = 0.f;
    float O[8][4];
#pragma unroll
    for (int i = 0; i < 8; i++)
#pragma unroll
        for (int j = 0; j < 4; j++) O[i][j] = 0.f;

    const int rq0 = 16 * wid + (lane >> 2);
    const int rq1 = rq0 + 8;

    for (int kt = 0; kt < 8; kt++) {
        const int k0t = kt * 64;
        const int basek = base0 + k0t;
        __syncthreads();   // prior tile fully done (PV reads, G-block writes)

        // ---- stage K splits, Es, mask ----
        for (int i = tid; i < 512; i += 128) {
            int row = i >> 3, c = i & 7;
            size_t g = (size_t)(b * SEQ + k0t + row) * 1024 + h * 64 + c * 8;
            *(uint4*)(smc + SM_KH + (row * RS + c * 8) * 2) = *(const uint4*)(g_xhi + g);
            *(uint4*)(smc + SM_KL + (row * RS + c * 8) * 2) = *(const uint4*)(g_xlo + g);
        }
        if (tid < 127) Es[tid] = g_E[h * 1024 + basek + tid];
        if (tid < 64) mk[tid] = (float)mask[b * SEQ + k0t + tid];
        __syncthreads();

        // ---- AC = A1 @ K^T ----
        float acc[8][4];
#pragma unroll
        for (int i = 0; i < 8; i++)
#pragma unroll
            for (int j = 0; j < 4; j++) acc[i][j] = 0.f;
        {
            int rowBg = (qd >> 1) * 8 + lr;
#pragma unroll
            for (int nb = 0; nb < 4; nb++) {
#pragma unroll
                for (int ks = 0; ks < 4; ks++) {
                    int colB = ks * 16 + (qd & 1) * 8;
                    uint32_t off = (uint32_t)((nb * 16 + rowBg) * RS + colB) * 2;
                    uint32_t kh4[4], kl4[4];
                    ldmatrix_x4(kh4, sb + SM_KH + off);
                    ldmatrix_x4(kl4, sb + SM_KL + off);
                    mma_bf16(acc[nb * 2], a1h[ks], kh4);
                    mma_bf16(acc[nb * 2], a1h[ks], kl4);
                    mma_bf16(acc[nb * 2], a1l[ks], kh4);
                    mma_bf16(acc[nb * 2 + 1], a1h[ks], kh4 + 2);
                    mma_bf16(acc[nb * 2 + 1], a1h[ks], kl4 + 2);
                    mma_bf16(acc[nb * 2 + 1], a1l[ks], kh4 + 2);
                }
            }
        }

        // ---- combine: S = AC + G(ring gather) + E, mask, online softmax ----
        float rmax0 = -1e30f, rmax1 = -1e30f;
#pragma unroll
        for (int nt = 0; nt < 8; nt++) {
            int c0 = nt * 8 + (lane & 3) * 2;
#pragma unroll
            for (int e = 0; e < 4; e++) {
                int q = (e < 2) ? rq0 : rq1;
                int k = c0 + (e & 1);
                int jj = k - q + 63;
                int gg = 64 * kt + jj;
                int slot = (gg >> 6) & 1;
                int col = gg & 63;
                float s = acc[nt][e] + Gs[q * 136 + slot * 68 + col] + Es[jj];
                float mv = mk[k];
                s = s * mv - (1.f - mv) * 1e8f;
                acc[nt][e] = s;
                if (e < 2) rmax0 = fmaxf(rmax0, s); else rmax1 = fmaxf(rmax1, s);
            }
        }
        rmax0 = fmaxf(rmax0, __shfl_xor_sync(0xffffffffu, rmax0, 1));
        rmax0 = fmaxf(rmax0, __shfl_xor_sync(0xffffffffu, rmax0, 2));
        rmax1 = fmaxf(rmax1, __shfl_xor_sync(0xffffffffu, rmax1, 1));
        rmax1 = fmaxf(rmax1, __shfl_xor_sync(0xffffffffu, rmax1, 2));
        float mn0 = fmaxf(m0, rmax0), mn1 = fmaxf(m1, rmax1);
        float sc0 = __expf(m0 - mn0), sc1 = __expf(m1 - mn1);
        m0 = mn0; m1 = mn1;
        float rs0 = 0.f, rs1 = 0.f;
#pragma unroll
        for (int nt = 0; nt < 8; nt++) {
#pragma unroll
            for (int e = 0; e < 4; e++) {
                float p = __expf(acc[nt][e] - ((e < 2) ? mn0 : mn1));
                acc[nt][e] = p;
                if (e < 2) rs0 += p; else rs1 += p;
            }
        }
        rs0 += __shfl_xor_sync(0xffffffffu, rs0, 1);
        rs0 += __shfl_xor_sync(0xffffffffu, rs0, 2);
        rs1 += __shfl_xor_sync(0xffffffffu, rs1, 1);
        rs1 += __shfl_xor_sync(0xffffffffu, rs1, 2);
        l0 = l0 * sc0 + rs0;
        l1 = l1 * sc1 + rs1;
#pragma unroll
        for (int nt = 0; nt < 8; nt++) {
            O[nt][0] *= sc0; O[nt][1] *= sc0;
            O[nt][2] *= sc1; O[nt][3] *= sc1;
        }
        __syncthreads();   // gathers + K reads done (Gs slot kt&1 / K region reusable)

        // ---- P splits (into alias region); stage V over K; stage next pos ----
#pragma unroll
        for (int nt = 0; nt < 8; nt++) {
            int c0 = nt * 8 + (lane & 3) * 2;
            __nv_bfloat16 h0 = __float2bfloat16(acc[nt][0]);
            __nv_bfloat16 h1 = __float2bfloat16(acc[nt][1]);
            __nv_bfloat16 h2 = __float2bfloat16(acc[nt][2]);
            __nv_bfloat16 h3 = __float2bfloat16(acc[nt][3]);
            __nv_bfloat16 e0 = __float2bfloat16(acc[nt][0] - __bfloat162float(h0));
            __nv_bfloat16 e1 = __float2bfloat16(acc[nt][1] - __bfloat162float(h1));
            __nv_bfloat16 e2 = __float2bfloat16(acc[nt][2] - __bfloat162float(h2));
            __nv_bfloat16 e3 = __float2bfloat16(acc[nt][3] - __bfloat162float(h3));
            *(uint32_t*)(smc + SM_PH + (rq0 * RS + c0) * 2) = pack2(h0, h1);
            *(uint32_t*)(smc + SM_PH + (rq1 * RS + c0) * 2) = pack2(h2, h3);
            *(uint32_t*)(smc + SM_PL + (rq0 * RS + c0) * 2) = pack2(e0, e1);
            *(uint32_t*)(smc + SM_PL + (rq1 * RS + c0) * 2) = pack2(e2, e3);
        }
        for (int i = tid; i < 512; i += 128) {
            int row = i >> 3, c = i & 7;
            size_t g = (size_t)(b * SEQ + k0t + row) * 1024 + h * 64 + c * 8;
            *(uint4*)(smc + SM_KH + (row * RS + c * 8) * 2) = *(const uint4*)(g_vhi + g);
            *(uint4*)(smc + SM_KL + (row * RS + c * 8) * 2) = *(const uint4*)(g_vlo + g);
        }
        if (kt < 7) {
            int pbase = base0 + 64 * (kt + 2);
            for (int i = tid; i < 512; i += 128) {
                int row = i >> 3, c = i & 7;
                int j = pbase + row; if (j > 1023) j = 1023;
                size_t g = (size_t)j * 64 + c * 8;
                *(uint4*)(smc + SM_POSH + (row * RS + c * 8) * 2) = *(const uint4*)(g_push + g);
                *(uint4*)(smc + SM_POSL + (row * RS + c * 8) * 2) = *(const uint4*)(g_posl + g);
            }
        }
        __syncthreads();

        // ---- O += P @ V ; compute G block kt+2 into slot kt&1 ----
        {
            int rowP = 16 * wid + (qd & 1) * 8 + lr;
#pragma unroll
            for (int ks = 0; ks < 4; ks++) {
                int colP = ks * 16 + (qd >> 1) * 8;
                uint32_t ap[4], al[4];
                ldmatrix_x4(ap, sb + SM_PH + (uint32_t)(rowP * RS + colP) * 2);
                ldmatrix_x4(al, sb + SM_PL + (uint32_t)(rowP * RS + colP) * 2);
                int rowV = ks * 16 + (qd & 1) * 8 + lr;
#pragma unroll
                for (int dt = 0; dt < 4; dt++) {
                    int colV = dt * 16 + (qd >> 1) * 8;
                    uint32_t off = (uint32_t)(rowV * RS + colV) * 2;
                    uint32_t vh[4], vl[4];
                    ldmatrix_x4_t(vh, sb + SM_KH + off);
                    ldmatrix_x4_t(vl, sb + SM_KL + off);
                    mma_bf16(O[dt * 2], ap, vh);
                    mma_bf16(O[dt * 2], ap, vl);
                    mma_bf16(O[dt * 2], al, vh);
                    mma_bf16(O[dt * 2 + 1], ap, vh + 2);
                    mma_bf16(O[dt * 2 + 1], ap, vl + 2);
                    mma_bf16(O[dt * 2 + 1], al, vh + 2);
                }
            }
        }
        if (kt < 7) g_block(sb, Gs, a1h, a1l, wid, lane, kt & 1);
    }

    // ---- epilogue: out = O / l ----
    float li0 = 1.f / l0, li1 = 1.f / l1;
#pragma unroll
    for (int nt = 0; nt < 8; nt++) {
        int col = h * 64 + nt * 8 + (lane & 3) * 2;
        size_t r0o = (size_t)(b * SEQ + q0 + rq0) * DM + col;
        size_t r1o = (size_t)(b * SEQ + q0 + rq1) * DM + col;
        *(float2*)(out + r0o) = make_float2(O[nt][0] * li0, O[nt][1] * li0);
        *(float2*)(out + r1o) = make_float2(O[nt][2] * li1, O[nt][3] * li1);
    }
}

// ---------------------------------------------------------------------------
extern "C" void kernel_launch(void* const* d_in, const int* in_sizes, int n_in,
                              void* d_out, int out_size) {
    const float* x   = (const float*)d_in[0];
    const int*   msk = (const int*)d_in[1];
    const float* Wqv = (const float*)d_in[2];
    const float* rr  = (const float*)d_in[3];
    const float* rw  = (const float*)d_in[4];
    float* out = (float*)d_out;

    cudaFuncSetAttribute(k_attn, cudaFuncAttributeMaxDynamicSharedMemorySize, SM_ATTN_TOT);
    cudaFuncSetAttribute(k_mm, cudaFuncAttributeMaxDynamicSharedMemorySize, 3 * STAGE_B);

    k_cvt_x<<<4096, 256>>>(x);
    k_cvt_w<<<dim3(64, 32), dim3(32, 8)>>>(Wqv);
    k_pos<<<256, 256>>>();
    k_E<<<dim3(8, 16), 128>>>(rr, rw);
    k_mm<<<dim3(16, 32), 256, 3 * STAGE_B>>>(rr);
    k_attn<<<dim3(8, 128), 128, SM_ATTN_TOT>>>(msk, out);
}

// round 11
// speedup vs baseline: 1.9816x; 1.1779x over previous
#include <cuda_runtime.h>
#include <cuda_bf16.h>
#include <math.h>
#include <cstdint>

#define NB 8
#define SEQ 512
#define DM 1024
#define NH 16
#define HDIM 64

// ---------------- scratch (static __device__: allocation-guard safe) -------
__device__ float g_pos[1024 * 64];            // relative positional table (fp32)
__device__ float g_E[16 * 1024];              // (r_w - r_r) . pos[j]
__device__ __nv_bfloat16 g_xhi[4096 * 1024];  // x split hi (K operand)
__device__ __nv_bfloat16 g_xlo[4096 * 1024];  // x split lo
__device__ __nv_bfloat16 g_whi[2048 * 1024];  // Wqv^T split hi  [n][k]
__device__ __nv_bfloat16 g_wlo[2048 * 1024];  // Wqv^T split lo
__device__ __nv_bfloat16 g_push[1024 * 64];   // pos split hi
__device__ __nv_bfloat16 g_posl[1024 * 64];   // pos split lo
__device__ __nv_bfloat16 g_qhi[4096 * 1024];  // A1 = q + r_r split hi
__device__ __nv_bfloat16 g_qlo[4096 * 1024];  // A1 split lo
__device__ __nv_bfloat16 g_vhi[4096 * 1024];  // V split hi
__device__ __nv_bfloat16 g_vlo[4096 * 1024];  // V split lo

// ---------------- helpers ---------------------------------------------------
__device__ __forceinline__ uint32_t smem_u32(const void* p) {
    uint32_t a;
    asm("{ .reg .u64 t; cvta.to.shared.u64 t, %1; cvt.u32.u64 %0, t; }" : "=r"(a) : "l"(p));
    return a;
}
__device__ __forceinline__ void ldmatrix_x4(uint32_t* r, uint32_t addr) {
    asm volatile("ldmatrix.sync.aligned.m8n8.x4.shared.b16 {%0,%1,%2,%3}, [%4];"
                 : "=r"(r[0]), "=r"(r[1]), "=r"(r[2]), "=r"(r[3]) : "r"(addr));
}
__device__ __forceinline__ void ldmatrix_x4_t(uint32_t* r, uint32_t addr) {
    asm volatile("ldmatrix.sync.aligned.m8n8.x4.trans.shared.b16 {%0,%1,%2,%3}, [%4];"
                 : "=r"(r[0]), "=r"(r[1]), "=r"(r[2]), "=r"(r[3]) : "r"(addr));
}
__device__ __forceinline__ void mma_bf16(float* c, const uint32_t* a, const uint32_t* b) {
    asm volatile("mma.sync.aligned.m16n8k16.row.col.f32.bf16.bf16.f32 "
                 "{%0,%1,%2,%3}, {%4,%5,%6,%7}, {%8,%9}, {%0,%1,%2,%3};"
                 : "+f"(c[0]), "+f"(c[1]), "+f"(c[2]), "+f"(c[3])
                 : "r"(a[0]), "r"(a[1]), "r"(a[2]), "r"(a[3]), "r"(b[0]), "r"(b[1]));
}
__device__ __forceinline__ void cp_async16(uint32_t saddr, const void* gaddr) {
    asm volatile("cp.async.cg.shared.global [%0], [%1], 16;" ::"r"(saddr), "l"(gaddr));
}
#define CP_COMMIT() asm volatile("cp.async.commit_group;" ::: "memory")
#define CP_WAIT(N) asm volatile("cp.async.wait_group %0;" ::"n"(N) : "memory")

__device__ __forceinline__ uint32_t pack2(__nv_bfloat16 lo, __nv_bfloat16 hi) {
    uint16_t a = *(uint16_t*)&lo, b = *(uint16_t*)&hi;
    return (uint32_t)a | ((uint32_t)b << 16);
}
__device__ __forceinline__ void store_split(__nv_bfloat16* hi, __nv_bfloat16* lo,
                                            size_t idx, float a, float b) {
    __nv_bfloat16 ha = __float2bfloat16(a), hb = __float2bfloat16(b);
    __nv_bfloat16 la = __float2bfloat16(a - __bfloat162float(ha));
    __nv_bfloat16 lb = __float2bfloat16(b - __bfloat162float(hb));
    *(uint32_t*)(hi + idx) = pack2(ha, hb);
    *(uint32_t*)(lo + idx) = pack2(la, lb);
}

// ---------------------------------------------------------------------------
// prep kernels (unchanged)
// ---------------------------------------------------------------------------
__global__ void k_cvt_x(const float* __restrict__ x) {
    int i = (blockIdx.x * blockDim.x + threadIdx.x) * 4;
    float4 v = *(const float4*)(x + i);
    float a[4] = {v.x, v.y, v.z, v.w};
    __nv_bfloat16 h[4], l[4];
#pragma unroll
    for (int j = 0; j < 4; j++) {
        h[j] = __float2bfloat16(a[j]);
        l[j] = __float2bfloat16(a[j] - __bfloat162float(h[j]));
    }
    *(uint2*)(g_xhi + i) = *(uint2*)h;
    *(uint2*)(g_xlo + i) = *(uint2*)l;
}

__global__ void k_cvt_w(const float* __restrict__ W) {
    __shared__ float t[32][33];
    int tx = threadIdx.x, ty = threadIdx.y;
    int n0 = blockIdx.x * 32, k0 = blockIdx.y * 32;
#pragma unroll
    for (int i = 0; i < 4; i++)
        t[ty + i * 8][tx] = W[(size_t)(k0 + ty + i * 8) * 2048 + n0 + tx];
    __syncthreads();
#pragma unroll
    for (int i = 0; i < 4; i++) {
        int n = n0 + ty + i * 8;
        float v = t[tx][ty + i * 8];
        __nv_bfloat16 h = __float2bfloat16(v);
        g_whi[(size_t)n * 1024 + k0 + tx] = h;
        g_wlo[(size_t)n * 1024 + k0 + tx] = __float2bfloat16(v - __bfloat162float(h));
    }
}

__global__ void k_pos() {
    int idx = blockIdx.x * blockDim.x + threadIdx.x;
    if (idx >= 1024 * 64) return;
    int j = idx >> 6;
    int i = idx & 63;
    const float C = -logf(10000.0f) / 31.0f;
    int ii = (i < 32) ? i : (i - 32);
    float freq = expf((float)ii * C);
    float arg = (float)(j - 512) * freq;
    float v = (i < 32) ? sinf(arg) : cosf(arg);
    g_pos[idx] = v;
    __nv_bfloat16 h = __float2bfloat16(v);
    g_push[idx] = h;
    g_posl[idx] = __float2bfloat16(v - __bfloat162float(h));
}

__global__ void k_E(const float* __restrict__ rr, const float* __restrict__ rw) {
    int j = blockIdx.x * 128 + threadIdx.x;
    int h = blockIdx.y;
    const float4* pp = (const float4*)(g_pos + (size_t)j * 64);
    const float4* pr = (const float4*)(rr + h * 64);
    const float4* pw = (const float4*)(rw + h * 64);
    float s = 0.f;
#pragma unroll
    for (int d = 0; d < 16; d++) {
        float4 p = pp[d], a = pw[d], bq = pr[d];
        s += (a.x - bq.x) * p.x + (a.y - bq.y) * p.y +
             (a.z - bq.z) * p.z + (a.w - bq.w) * p.w;
    }
    g_E[h * 1024 + j] = s;
}

// ---------------------------------------------------------------------------
// qv = x @ Wqv via mma.sync bf16 2-split; 3-stage cp.async (proven R10)
// ---------------------------------------------------------------------------
#define RS 72
#define TILE_B 18432
#define STAGE_B 73728

__global__ void __launch_bounds__(256) k_mm(const float* __restrict__ rr) {
    extern __shared__ __nv_bfloat16 smb[];
    const uint32_t sb = smem_u32(smb);
    const int tid = threadIdx.x;
    const int wid = tid >> 5, lane = tid & 31;
    const int m0 = blockIdx.y * 128, n0 = blockIdx.x * 128;

    const __nv_bfloat16* src0 = g_xhi + (size_t)m0 * 1024;
    const __nv_bfloat16* src1 = g_xlo + (size_t)m0 * 1024;
    const __nv_bfloat16* src2 = g_whi + (size_t)n0 * 1024;
    const __nv_bfloat16* src3 = g_wlo + (size_t)n0 * 1024;

    const int p_row = tid >> 1;
    const int p_c0 = (tid & 1) * 2;

    const int wm = wid >> 1, wn = wid & 1;
    const int m_base = wm * 32, n_base = wn * 64;
    const int lr = lane & 7, q = lane >> 3;

    float acc[2][8][4];
#pragma unroll
    for (int i = 0; i < 2; i++)
#pragma unroll
        for (int j = 0; j < 8; j++)
#pragma unroll
            for (int k = 0; k < 4; k++) acc[i][j][k] = 0.f;

#define PREFETCH(KT, STAGE)                                                              \
    do {                                                                                 \
        const int _k0 = (KT) * 32;                                                       \
        const uint32_t _stg = sb + (STAGE) * STAGE_B;                                    \
        const uint32_t _soff = (uint32_t)(p_row * RS) * 2 + p_c0 * 16;                   \
        const size_t _goff = (size_t)p_row * 1024 + _k0 + p_c0 * 8;                      \
        cp_async16(_stg + _soff, src0 + _goff);                                          \
        cp_async16(_stg + _soff + 16, src0 + _goff + 8);                                 \
        cp_async16(_stg + TILE_B + _soff, src1 + _goff);                                 \
        cp_async16(_stg + TILE_B + _soff + 16, src1 + _goff + 8);                        \
        cp_async16(_stg + 2 * TILE_B + _soff, src2 + _goff);                             \
        cp_async16(_stg + 2 * TILE_B + _soff + 16, src2 + _goff + 8);                    \
        cp_async16(_stg + 3 * TILE_B + _soff, src3 + _goff);                             \
        cp_async16(_stg + 3 * TILE_B + _soff + 16, src3 + _goff + 8);                    \
    } while (0)

    PREFETCH(0, 0);
    CP_COMMIT();
    PREFETCH(1, 1);
    CP_COMMIT();

    for (int kt = 0; kt < 32; kt++) {
        if (kt + 2 < 32) {
            const int st2 = (kt + 2) % 3;
            PREFETCH(kt + 2, st2);
        }
        CP_COMMIT();
        CP_WAIT(2);
        __syncthreads();

        const uint32_t stg = sb + (kt % 3) * STAGE_B;
        const uint32_t bAh = stg, bAl = stg + TILE_B;
        const uint32_t bBh = stg + 2 * TILE_B, bBl = stg + 3 * TILE_B;

#pragma unroll
        for (int kk = 0; kk < 32; kk += 16) {
            uint32_t bh[8][2], bl[8][2];
#pragma unroll
            for (int nb = 0; nb < 4; nb++) {
                int rown = n_base + nb * 16 + ((q >> 1) * 8) + lr;
                int colk = kk + (q & 1) * 8;
                uint32_t off = (uint32_t)(rown * RS + colk) * 2;
                uint32_t r4[4];
                ldmatrix_x4(r4, bBh + off);
                bh[nb * 2][0] = r4[0]; bh[nb * 2][1] = r4[1];
                bh[nb * 2 + 1][0] = r4[2]; bh[nb * 2 + 1][1] = r4[3];
                ldmatrix_x4(r4, bBl + off);
                bl[nb * 2][0] = r4[0]; bl[nb * 2][1] = r4[1];
                bl[nb * 2 + 1][0] = r4[2]; bl[nb * 2 + 1][1] = r4[3];
            }
#pragma unroll
            for (int mb = 0; mb < 2; mb++) {
                int rowm = m_base + mb * 16 + ((q & 1) * 8) + lr;
                int colk = kk + (q >> 1) * 8;
                uint32_t off = (uint32_t)(rowm * RS + colk) * 2;
                uint32_t ah[4], al[4];
                ldmatrix_x4(ah, bAh + off);
                ldmatrix_x4(al, bAl + off);
#pragma unroll
                for (int nb = 0; nb < 8; nb++) {
                    mma_bf16(acc[mb][nb], ah, bh[nb]);
                    mma_bf16(acc[mb][nb], ah, bl[nb]);
                    mma_bf16(acc[mb][nb], al, bh[nb]);
                }
            }
        }
        __syncthreads();
    }

#pragma unroll
    for (int mb = 0; mb < 2; mb++) {
        int row0 = m0 + m_base + mb * 16 + (lane >> 2);
#pragma unroll
        for (int nb = 0; nb < 8; nb++) {
            int col = n0 + n_base + nb * 8 + (lane & 3) * 2;
            if (col < 1024) {
                float2 rb = *(const float2*)(rr + col);
                store_split(g_qhi, g_qlo, (size_t)row0 * 1024 + col,
                            acc[mb][nb][0] + rb.x, acc[mb][nb][1] + rb.y);
                store_split(g_qhi, g_qlo, (size_t)(row0 + 8) * 1024 + col,
                            acc[mb][nb][2] + rb.x, acc[mb][nb][3] + rb.y);
            } else {
                int c2 = col - 1024;
                store_split(g_vhi, g_vlo, (size_t)row0 * 1024 + c2,
                            acc[mb][nb][0], acc[mb][nb][1]);
                store_split(g_vhi, g_vlo, (size_t)(row0 + 8) * 1024 + c2,
                            acc[mb][nb][2], acc[mb][nb][3]);
            }
        }
    }
#undef PREFETCH
}

// ---------------------------------------------------------------------------
// Tensor-core fused attention: cp.async staging, K double-buffer, E folded
// into the G ring at store time.
// Smem: K/V ping-pong 2x18432 | pos 18432 | Gs[64][2][68] fp32 | P hi/lo | mk
// ---------------------------------------------------------------------------
#define SM_KBUF(bf) ((bf) * 18432)      // hi +0, lo +9216
#define SM_POSH 36864
#define SM_POSL 46080
#define SM_GS   55296
#define SM_PH   90112
#define SM_PL   99328
#define SM_MK   108544
#define SM_ATTN_TOT 108800

// G block blk (64 pos cols starting at global col 64*blk) -> ring slot blk&1.
// E is folded in at store time: Gs = A1@posWin^T + E.
__device__ __forceinline__ void g_block(uint32_t sb, float* Gs,
                                        const uint32_t (&a1h)[4][4],
                                        const uint32_t (&a1l)[4][4],
                                        int wid, int lane, int blk,
                                        const float* __restrict__ Eh, int base0) {
    const int lr = lane & 7, qd = lane >> 3;
    const int rowBg = (qd >> 1) * 8 + lr;
    const int rg = 16 * wid + (lane >> 2);
    const int cgl = (lane & 3) * 2;
    const int slot = blk & 1;
#pragma unroll
    for (int nb = 0; nb < 4; nb++) {
        float g0[4] = {0.f, 0.f, 0.f, 0.f}, g1[4] = {0.f, 0.f, 0.f, 0.f};
#pragma unroll
        for (int ks = 0; ks < 4; ks++) {
            int colB = ks * 16 + (qd & 1) * 8;
            uint32_t off = (uint32_t)((nb * 16 + rowBg) * RS + colB) * 2;
            uint32_t bh4[4], bl4[4];
            ldmatrix_x4(bh4, sb + SM_POSH + off);
            ldmatrix_x4(bl4, sb + SM_POSL + off);
            mma_bf16(g0, a1h[ks], bh4);
            mma_bf16(g0, a1h[ks], bl4);
            mma_bf16(g0, a1l[ks], bh4);
            mma_bf16(g1, a1h[ks], bh4 + 2);
            mma_bf16(g1, a1h[ks], bl4 + 2);
            mma_bf16(g1, a1l[ks], bh4 + 2);
        }
        int cg = nb * 16 + cgl;
        int gi = base0 + blk * 64 + cg;     // E index of col cg (>=1 always)
        float e0 = Eh[min(gi, 1023)];
        float e1 = Eh[min(gi + 1, 1023)];
        float e8 = Eh[min(gi + 8, 1023)];
        float e9 = Eh[min(gi + 9, 1023)];
        int bq = rg * 136 + slot * 68;
        *(float2*)&Gs[bq + cg] = make_float2(g0[0] + e0, g0[1] + e1);
        *(float2*)&Gs[bq + 8 * 136 + cg] = make_float2(g0[2] + e0, g0[3] + e1);
        *(float2*)&Gs[bq + cg + 8] = make_float2(g1[0] + e8, g1[1] + e9);
        *(float2*)&Gs[bq + 8 * 136 + cg + 8] = make_float2(g1[2] + e8, g1[3] + e9);
    }
}

__global__ void __launch_bounds__(128) k_attn(const int* __restrict__ mask,
                                              float* __restrict__ out) {
    extern __shared__ char smc[];
    const uint32_t sb = smem_u32(smc);
    float* Gs = (float*)(smc + SM_GS);
    float* mk = (float*)(smc + SM_MK);

    const int tid = threadIdx.x;
    const int wid = tid >> 5, lane = tid & 31;
    const int lr = lane & 7, qd = lane >> 3;
    const int bh = blockIdx.y;
    const int b = bh >> 4, h = bh & 15;
    const int q0 = blockIdx.x * 64;
    const int base0 = 449 - q0;
    const float* Eh = g_E + h * 1024;

    // ---- prologue: stage A1 splits (into P alias region) ----
    for (int i = tid; i < 512; i += 128) {
        int row = i >> 3, c = i & 7;
        size_t g = (size_t)(b * SEQ + q0 + row) * 1024 + h * 64 + c * 8;
        *(uint4*)(smc + SM_PH + (row * RS + c * 8) * 2) = *(const uint4*)(g_qhi + g);
        *(uint4*)(smc + SM_PL + (row * RS + c * 8) * 2) = *(const uint4*)(g_qlo + g);
    }
    if (tid < 64) mk[tid] = (float)mask[b * SEQ + tid];
    __syncthreads();

    uint32_t a1h[4][4], a1l[4][4];
    {
        int rowA = 16 * wid + (qd & 1) * 8 + lr;
#pragma unroll
        for (int ks = 0; ks < 4; ks++) {
            int colA = ks * 16 + (qd >> 1) * 8;
            ldmatrix_x4(a1h[ks], sb + SM_PH + (uint32_t)(rowA * RS + colA) * 2);
            ldmatrix_x4(a1l[ks], sb + SM_PL + (uint32_t)(rowA * RS + colA) * 2);
        }
    }

    // issue K(0) prefetch
    for (int i = tid; i < 512; i += 128) {
        int row = i >> 3, c = i & 7;
        size_t g = (size_t)(b * SEQ + row) * 1024 + h * 64 + c * 8;
        uint32_t d = sb + SM_KBUF(0) + (row * RS + c * 8) * 2;
        cp_async16(d, g_xhi + g);
        cp_async16(d + 9216, g_xlo + g);
    }
    CP_COMMIT();

    // ---- prologue: G blocks 0 and 1 ----
#pragma unroll
    for (int bi = 0; bi < 2; bi++) {
        int pbase = base0 + 64 * bi;
        for (int i = tid; i < 512; i += 128) {
            int row = i >> 3, c = i & 7;
            int j = pbase + row; if (j > 1023) j = 1023;
            size_t g = (size_t)j * 64 + c * 8;
            uint32_t d = (row * RS + c * 8) * 2;
            cp_async16(sb + SM_POSH + d, g_push + g);
            cp_async16(sb + SM_POSL + d, g_posl + g);
        }
        CP_COMMIT();
        CP_WAIT(0);
        __syncthreads();
        g_block(sb, Gs, a1h, a1l, wid, lane, bi, Eh, base0);
        __syncthreads();
    }

    float m0 = -1e30f, m1 = -1e30f, l0 = 0.f, l1 = 0.f;
    float O[8][4];
#pragma unroll
    for (int i = 0; i < 8; i++)
#pragma unroll
        for (int j = 0; j < 4; j++) O[i][j] = 0.f;

    const int rq0 = 16 * wid + (lane >> 2);
    const int rq1 = rq0 + 8;

    for (int kt = 0; kt < 8; kt++) {
        const int k0t = kt * 64;
        const uint32_t kb = sb + SM_KBUF(kt & 1);
        __syncthreads();   // prior tile's PV/g_block reads complete

        // ---- AC = A1 @ K^T (K already resident in kb) ----
        float acc[8][4];
#pragma unroll
        for (int i = 0; i < 8; i++)
#pragma unroll
            for (int j = 0; j < 4; j++) acc[i][j] = 0.f;
        {
            int rowBg = (qd >> 1) * 8 + lr;
#pragma unroll
            for (int nb = 0; nb < 4; nb++) {
#pragma unroll
                for (int ks = 0; ks < 4; ks++) {
                    int colB = ks * 16 + (qd & 1) * 8;
                    uint32_t off = (uint32_t)((nb * 16 + rowBg) * RS + colB) * 2;
                    uint32_t kh4[4], kl4[4];
                    ldmatrix_x4(kh4, kb + off);
                    ldmatrix_x4(kl4, kb + 9216 + off);
                    mma_bf16(acc[nb * 2], a1h[ks], kh4);
                    mma_bf16(acc[nb * 2], a1h[ks], kl4);
                    mma_bf16(acc[nb * 2], a1l[ks], kh4);
                    mma_bf16(acc[nb * 2 + 1], a1h[ks], kh4 + 2);
                    mma_bf16(acc[nb * 2 + 1], a1h[ks], kl4 + 2);
                    mma_bf16(acc[nb * 2 + 1], a1l[ks], kh4 + 2);
                }
            }
        }

        // ---- combine: S = AC + Gs(ring, E folded), mask, online softmax ----
        float rmax0 = -1e30f, rmax1 = -1e30f;
#pragma unroll
        for (int nt = 0; nt < 8; nt++) {
            int c0 = nt * 8 + (lane & 3) * 2;
#pragma unroll
            for (int e = 0; e < 4; e++) {
                int q = (e < 2) ? rq0 : rq1;
                int k = c0 + (e & 1);
                int gg = 64 * kt + k - q + 63;
                int slot = (gg >> 6) & 1;
                int col = gg & 63;
                float s = acc[nt][e] + Gs[q * 136 + slot * 68 + col];
                float mv = mk[k];
                s = s * mv - (1.f - mv) * 1e8f;
                acc[nt][e] = s;
                if (e < 2) rmax0 = fmaxf(rmax0, s); else rmax1 = fmaxf(rmax1, s);
            }
        }
        rmax0 = fmaxf(rmax0, __shfl_xor_sync(0xffffffffu, rmax0, 1));
        rmax0 = fmaxf(rmax0, __shfl_xor_sync(0xffffffffu, rmax0, 2));
        rmax1 = fmaxf(rmax1, __shfl_xor_sync(0xffffffffu, rmax1, 1));
        rmax1 = fmaxf(rmax1, __shfl_xor_sync(0xffffffffu, rmax1, 2));
        float mn0 = fmaxf(m0, rmax0), mn1 = fmaxf(m1, rmax1);
        float sc0 = __expf(m0 - mn0), sc1 = __expf(m1 - mn1);
        m0 = mn0; m1 = mn1;
        float rs0 = 0.f, rs1 = 0.f;
#pragma unroll
        for (int nt = 0; nt < 8; nt++) {
#pragma unroll
            for (int e = 0; e < 4; e++) {
                float p = __expf(acc[nt][e] - ((e < 2) ? mn0 : mn1));
                acc[nt][e] = p;
                if (e < 2) rs0 += p; else rs1 += p;
            }
        }
        rs0 += __shfl_xor_sync(0xffffffffu, rs0, 1);
        rs0 += __shfl_xor_sync(0xffffffffu, rs0, 2);
        rs1 += __shfl_xor_sync(0xffffffffu, rs1, 1);
        rs1 += __shfl_xor_sync(0xffffffffu, rs1, 2);
        l0 = l0 * sc0 + rs0;
        l1 = l1 * sc1 + rs1;
#pragma unroll
        for (int nt = 0; nt < 8; nt++) {
            O[nt][0] *= sc0; O[nt][1] *= sc0;
            O[nt][2] *= sc1; O[nt][3] *= sc1;
        }
        __syncthreads();   // K/Gs reads done; buffers reusable

        // ---- post phase: fire-and-forget cp.async (V, next K, next pos),
        //      overlapped with P-split scalar work ----
        for (int i = tid; i < 512; i += 128) {
            int row = i >> 3, c = i & 7;
            size_t g = (size_t)(b * SEQ + k0t + row) * 1024 + h * 64 + c * 8;
            uint32_t d = kb + (row * RS + c * 8) * 2;
            cp_async16(d, g_vhi + g);
            cp_async16(d + 9216, g_vlo + g);
        }
        if (kt < 7) {
            const uint32_t kb2 = sb + SM_KBUF((kt + 1) & 1);
            for (int i = tid; i < 512; i += 128) {
                int row = i >> 3, c = i & 7;
                size_t g = (size_t)(b * SEQ + k0t + 64 + row) * 1024 + h * 64 + c * 8;
                uint32_t d = kb2 + (row * RS + c * 8) * 2;
                cp_async16(d, g_xhi + g);
                cp_async16(d + 9216, g_xlo + g);
            }
            int pbase = base0 + 64 * (kt + 2);
            for (int i = tid; i < 512; i += 128) {
                int row = i >> 3, c = i & 7;
                int j = pbase + row; if (j > 1023) j = 1023;
                size_t g = (size_t)j * 64 + c * 8;
                uint32_t d = (row * RS + c * 8) * 2;
                cp_async16(sb + SM_POSH + d, g_push + g);
                cp_async16(sb + SM_POSL + d, g_posl + g);
            }
            if (tid < 64) mk[tid] = (float)mask[b * SEQ + k0t + 64 + tid];
        }
        CP_COMMIT();

        // P splits (smem STS; overlaps with cp.async flight)
#pragma unroll
        for (int nt = 0; nt < 8; nt++) {
            int c0 = nt * 8 + (lane & 3) * 2;
            __nv_bfloat16 h0 = __float2bfloat16(acc[nt][0]);
            __nv_bfloat16 h1 = __float2bfloat16(acc[nt][1]);
            __nv_bfloat16 h2 = __float2bfloat16(acc[nt][2]);
            __nv_bfloat16 h3 = __float2bfloat16(acc[nt][3]);
            __nv_bfloat16 e0 = __float2bfloat16(acc[nt][0] - __bfloat162float(h0));
            __nv_bfloat16 e1 = __float2bfloat16(acc[nt][1] - __bfloat162float(h1));
            __nv_bfloat16 e2 = __float2bfloat16(acc[nt][2] - __bfloat162float(h2));
            __nv_bfloat16 e3 = __float2bfloat16(acc[nt][3] - __bfloat162float(h3));
            *(uint32_t*)(smc + SM_PH + (rq0 * RS + c0) * 2) = pack2(h0, h1);
            *(uint32_t*)(smc + SM_PH + (rq1 * RS + c0) * 2) = pack2(h2, h3);
            *(uint32_t*)(smc + SM_PL + (rq0 * RS + c0) * 2) = pack2(e0, e1);
            *(uint32_t*)(smc + SM_PL + (rq1 * RS + c0) * 2) = pack2(e2, e3);
        }
        CP_WAIT(0);
        __syncthreads();

        // ---- O += P @ V ; compute G block kt+2 ----
        {
            int rowP = 16 * wid + (qd & 1) * 8 + lr;
#pragma unroll
            for (int ks = 0; ks < 4; ks++) {
                int colP = ks * 16 + (qd >> 1) * 8;
                uint32_t ap[4], al[4];
                ldmatrix_x4(ap, sb + SM_PH + (uint32_t)(rowP * RS + colP) * 2);
                ldmatrix_x4(al, sb + SM_PL + (uint32_t)(rowP * RS + colP) * 2);
                int rowV = ks * 16 + (qd & 1) * 8 + lr;
#pragma unroll
                for (int dt = 0; dt < 4; dt++) {
                    int colV = dt * 16 + (qd >> 1) * 8;
                    uint32_t off = (uint32_t)(rowV * RS + colV) * 2;
                    uint32_t vh[4], vl[4];
                    ldmatrix_x4_t(vh, kb + off);
                    ldmatrix_x4_t(vl, kb + 9216 + off);
                    mma_bf16(O[dt * 2], ap, vh);
                    mma_bf16(O[dt * 2], ap, vl);
                    mma_bf16(O[dt * 2], al, vh);
                    mma_bf16(O[dt * 2 + 1], ap, vh + 2);
                    mma_bf16(O[dt * 2 + 1], ap, vl + 2);
                    mma_bf16(O[dt * 2 + 1], al, vh + 2);
                }
            }
        }
        if (kt < 7) g_block(sb, Gs, a1h, a1l, wid, lane, kt + 2, Eh, base0);
    }

    // ---- epilogue: out = O / l ----
    float li0 = 1.f / l0, li1 = 1.f / l1;
#pragma unroll
    for (int nt = 0; nt < 8; nt++) {
        int col = h * 64 + nt * 8 + (lane & 3) * 2;
        size_t r0o = (size_t)(b * SEQ + q0 + rq0) * DM + col;
        size_t r1o = (size_t)(b * SEQ + q0 + rq1) * DM + col;
        *(float2*)(out + r0o) = make_float2(O[nt][0] * li0, O[nt][1] * li0);
        *(float2*)(out + r1o) = make_float2(O[nt][2] * li1, O[nt][3] * li1);
    }
}

// ---------------------------------------------------------------------------
extern "C" void kernel_launch(void* const* d_in, const int* in_sizes, int n_in,
                              void* d_out, int out_size) {
    const float* x   = (const float*)d_in[0];
    const int*   msk = (const int*)d_in[1];
    const float* Wqv = (const float*)d_in[2];
    const float* rr  = (const float*)d_in[3];
    const float* rw  = (const float*)d_in[4];
    float* out = (float*)d_out;

    cudaFuncSetAttribute(k_attn, cudaFuncAttributeMaxDynamicSharedMemorySize, SM_ATTN_TOT);
    cudaFuncSetAttribute(k_mm, cudaFuncAttributeMaxDynamicSharedMemorySize, 3 * STAGE_B);

    k_cvt_x<<<4096, 256>>>(x);
    k_cvt_w<<<dim3(64, 32), dim3(32, 8)>>>(Wqv);
    k_pos<<<256, 256>>>();
    k_E<<<dim3(8, 16), 128>>>(rr, rw);
    k_mm<<<dim3(16, 32), 256, 3 * STAGE_B>>>(rr);
    k_attn<<<dim3(8, 128), 128, SM_ATTN_TOT>>>(msk, out);
}

// round 14
// speedup vs baseline: 2.2256x; 1.1232x over previous
#include <cuda_runtime.h>
#include <cuda_bf16.h>
#include <cuda_fp16.h>
#include <math.h>
#include <cstdint>

#define NB 8
#define SEQ 512
#define DM 1024
#define NH 16
#define HDIM 64

// ---------------- scratch (static __device__: allocation-guard safe) -------
__device__ float g_pos[1024 * 64];            // relative positional table (fp32)
__device__ float g_E[16 * 1024];              // (r_w - r_r) . pos[j]
__device__ __nv_bfloat16 g_xhi[4096 * 1024];  // x split hi (K operand)
__device__ __nv_bfloat16 g_xlo[4096 * 1024];  // x split lo
__device__ __nv_bfloat16 g_whi[2048 * 1024];  // Wqv^T split hi  [n][k]
__device__ __nv_bfloat16 g_wlo[2048 * 1024];  // Wqv^T split lo
__device__ __nv_bfloat16 g_push[1024 * 64];   // pos split hi
__device__ __nv_bfloat16 g_posl[1024 * 64];   // pos split lo
__device__ __nv_bfloat16 g_qhi[4096 * 1024];  // A1 = q + r_r split hi
__device__ __nv_bfloat16 g_qlo[4096 * 1024];  // A1 split lo
__device__ unsigned short g_vf16[4096 * 1024];// V as fp16 (single precision)

// ---------------- helpers ---------------------------------------------------
__device__ __forceinline__ uint32_t smem_u32(const void* p) {
    uint32_t a;
    asm("{ .reg .u64 t; cvta.to.shared.u64 t, %1; cvt.u32.u64 %0, t; }" : "=r"(a) : "l"(p));
    return a;
}
__device__ __forceinline__ void ldmatrix_x4(uint32_t* r, uint32_t addr) {
    asm volatile("ldmatrix.sync.aligned.m8n8.x4.shared.b16 {%0,%1,%2,%3}, [%4];"
                 : "=r"(r[0]), "=r"(r[1]), "=r"(r[2]), "=r"(r[3]) : "r"(addr));
}
__device__ __forceinline__ void ldmatrix_x4_t(uint32_t* r, uint32_t addr) {
    asm volatile("ldmatrix.sync.aligned.m8n8.x4.trans.shared.b16 {%0,%1,%2,%3}, [%4];"
                 : "=r"(r[0]), "=r"(r[1]), "=r"(r[2]), "=r"(r[3]) : "r"(addr));
}
__device__ __forceinline__ void mma_bf16(float* c, const uint32_t* a, const uint32_t* b) {
    asm volatile("mma.sync.aligned.m16n8k16.row.col.f32.bf16.bf16.f32 "
                 "{%0,%1,%2,%3}, {%4,%5,%6,%7}, {%8,%9}, {%0,%1,%2,%3};"
                 : "+f"(c[0]), "+f"(c[1]), "+f"(c[2]), "+f"(c[3])
                 : "r"(a[0]), "r"(a[1]), "r"(a[2]), "r"(a[3]), "r"(b[0]), "r"(b[1]));
}
__device__ __forceinline__ void mma_f16(float* c, const uint32_t* a, const uint32_t* b) {
    asm volatile("mma.sync.aligned.m16n8k16.row.col.f32.f16.f16.f32 "
                 "{%0,%1,%2,%3}, {%4,%5,%6,%7}, {%8,%9}, {%0,%1,%2,%3};"
                 : "+f"(c[0]), "+f"(c[1]), "+f"(c[2]), "+f"(c[3])
                 : "r"(a[0]), "r"(a[1]), "r"(a[2]), "r"(a[3]), "r"(b[0]), "r"(b[1]));
}
__device__ __forceinline__ void cp_async16(uint32_t saddr, const void* gaddr) {
    asm volatile("cp.async.cg.shared.global [%0], [%1], 16;" ::"r"(saddr), "l"(gaddr));
}
#define CP_COMMIT() asm volatile("cp.async.commit_group;" ::: "memory")
#define CP_WAIT(N) asm volatile("cp.async.wait_group %0;" ::"n"(N) : "memory")

__device__ __forceinline__ uint32_t pack2(__nv_bfloat16 lo, __nv_bfloat16 hi) {
    uint16_t a = *(uint16_t*)&lo, b = *(uint16_t*)&hi;
    return (uint32_t)a | ((uint32_t)b << 16);
}
__device__ __forceinline__ void store_split(__nv_bfloat16* hi, __nv_bfloat16* lo,
                                            size_t idx, float a, float b) {
    __nv_bfloat16 ha = __float2bfloat16(a), hb = __float2bfloat16(b);
    __nv_bfloat16 la = __float2bfloat16(a - __bfloat162float(ha));
    __nv_bfloat16 lb = __float2bfloat16(b - __bfloat162float(hb));
    *(uint32_t*)(hi + idx) = pack2(ha, hb);
    *(uint32_t*)(lo + idx) = pack2(la, lb);
}

// ---------------------------------------------------------------------------
// prep kernels
// ---------------------------------------------------------------------------
__global__ void k_cvt_x(const float* __restrict__ x) {
    int i = (blockIdx.x * blockDim.x + threadIdx.x) * 4;
    float4 v = *(const float4*)(x + i);
    float a[4] = {v.x, v.y, v.z, v.w};
    __nv_bfloat16 h[4], l[4];
#pragma unroll
    for (int j = 0; j < 4; j++) {
        h[j] = __float2bfloat16(a[j]);
        l[j] = __float2bfloat16(a[j] - __bfloat162float(h[j]));
    }
    *(uint2*)(g_xhi + i) = *(uint2*)h;
    *(uint2*)(g_xlo + i) = *(uint2*)l;
}

__global__ void k_cvt_w(const float* __restrict__ W) {
    __shared__ float t[32][33];
    int tx = threadIdx.x, ty = threadIdx.y;
    int n0 = blockIdx.x * 32, k0 = blockIdx.y * 32;
#pragma unroll
    for (int i = 0; i < 4; i++)
        t[ty + i * 8][tx] = W[(size_t)(k0 + ty + i * 8) * 2048 + n0 + tx];
    __syncthreads();
#pragma unroll
    for (int i = 0; i < 4; i++) {
        int n = n0 + ty + i * 8;
        float v = t[tx][ty + i * 8];
        __nv_bfloat16 h = __float2bfloat16(v);
        g_whi[(size_t)n * 1024 + k0 + tx] = h;
        g_wlo[(size_t)n * 1024 + k0 + tx] = __float2bfloat16(v - __bfloat162float(h));
    }
}

__global__ void k_pos() {
    int idx = blockIdx.x * blockDim.x + threadIdx.x;
    if (idx >= 1024 * 64) return;
    int j = idx >> 6;
    int i = idx & 63;
    const float C = -logf(10000.0f) / 31.0f;
    int ii = (i < 32) ? i : (i - 32);
    float freq = expf((float)ii * C);
    float arg = (float)(j - 512) * freq;
    float v = (i < 32) ? sinf(arg) : cosf(arg);
    g_pos[idx] = v;
    __nv_bfloat16 h = __float2bfloat16(v);
    g_push[idx] = h;
    g_posl[idx] = __float2bfloat16(v - __bfloat162float(h));
}

__global__ void k_E(const float* __restrict__ rr, const float* __restrict__ rw) {
    int j = blockIdx.x * 128 + threadIdx.x;
    int h = blockIdx.y;
    const float4* pp = (const float4*)(g_pos + (size_t)j * 64);
    const float4* pr = (const float4*)(rr + h * 64);
    const float4* pw = (const float4*)(rw + h * 64);
    float s = 0.f;
#pragma unroll
    for (int d = 0; d < 16; d++) {
        float4 p = pp[d], a = pw[d], bq = pr[d];
        s += (a.x - bq.x) * p.x + (a.y - bq.y) * p.y +
             (a.z - bq.z) * p.z + (a.w - bq.w) * p.w;
    }
    g_E[h * 1024 + j] = s;
}

// ---------------------------------------------------------------------------
// qv = x @ Wqv via mma.sync bf16 2-split; 3-stage cp.async (proven R10/R11).
// Epilogue: A1=q+rr bf16 hi/lo splits; V as single fp16.
// ---------------------------------------------------------------------------
#define RS 72
#define TILE_B 18432
#define STAGE_B 73728

__global__ void __launch_bounds__(256) k_mm(const float* __restrict__ rr) {
    extern __shared__ __nv_bfloat16 smb[];
    const uint32_t sb = smem_u32(smb);
    const int tid = threadIdx.x;
    const int wid = tid >> 5, lane = tid & 31;
    const int m0 = blockIdx.y * 128, n0 = blockIdx.x * 128;

    const __nv_bfloat16* src0 = g_xhi + (size_t)m0 * 1024;
    const __nv_bfloat16* src1 = g_xlo + (size_t)m0 * 1024;
    const __nv_bfloat16* src2 = g_whi + (size_t)n0 * 1024;
    const __nv_bfloat16* src3 = g_wlo + (size_t)n0 * 1024;

    const int p_row = tid >> 1;
    const int p_c0 = (tid & 1) * 2;

    const int wm = wid >> 1, wn = wid & 1;
    const int m_base = wm * 32, n_base = wn * 64;
    const int lr = lane & 7, q = lane >> 3;

    float acc[2][8][4];
#pragma unroll
    for (int i = 0; i < 2; i++)
#pragma unroll
        for (int j = 0; j < 8; j++)
#pragma unroll
            for (int k = 0; k < 4; k++) acc[i][j][k] = 0.f;

#define PREFETCH(KT, STAGE)                                                              \
    do {                                                                                 \
        const int _k0 = (KT) * 32;                                                       \
        const uint32_t _stg = sb + (STAGE) * STAGE_B;                                    \
        const uint32_t _soff = (uint32_t)(p_row * RS) * 2 + p_c0 * 16;                   \
        const size_t _goff = (size_t)p_row * 1024 + _k0 + p_c0 * 8;                      \
        cp_async16(_stg + _soff, src0 + _goff);                                          \
        cp_async16(_stg + _soff + 16, src0 + _goff + 8);                                 \
        cp_async16(_stg + TILE_B + _soff, src1 + _goff);                                 \
        cp_async16(_stg + TILE_B + _soff + 16, src1 + _goff + 8);                        \
        cp_async16(_stg + 2 * TILE_B + _soff, src2 + _goff);                             \
        cp_async16(_stg + 2 * TILE_B + _soff + 16, src2 + _goff + 8);                    \
        cp_async16(_stg + 3 * TILE_B + _soff, src3 + _goff);                             \
        cp_async16(_stg + 3 * TILE_B + _soff + 16, src3 + _goff + 8);                    \
    } while (0)

    PREFETCH(0, 0);
    CP_COMMIT();
    PREFETCH(1, 1);
    CP_COMMIT();

    for (int kt = 0; kt < 32; kt++) {
        if (kt + 2 < 32) {
            const int st2 = (kt + 2) % 3;
            PREFETCH(kt + 2, st2);
        }
        CP_COMMIT();
        CP_WAIT(2);
        __syncthreads();

        const uint32_t stg = sb + (kt % 3) * STAGE_B;
        const uint32_t bAh = stg, bAl = stg + TILE_B;
        const uint32_t bBh = stg + 2 * TILE_B, bBl = stg + 3 * TILE_B;

#pragma unroll
        for (int kk = 0; kk < 32; kk += 16) {
            uint32_t bh[8][2], bl[8][2];
#pragma unroll
            for (int nb = 0; nb < 4; nb++) {
                int rown = n_base + nb * 16 + ((q >> 1) * 8) + lr;
                int colk = kk + (q & 1) * 8;
                uint32_t off = (uint32_t)(rown * RS + colk) * 2;
                uint32_t r4[4];
                ldmatrix_x4(r4, bBh + off);
                bh[nb * 2][0] = r4[0]; bh[nb * 2][1] = r4[1];
                bh[nb * 2 + 1][0] = r4[2]; bh[nb * 2 + 1][1] = r4[3];
                ldmatrix_x4(r4, bBl + off);
                bl[nb * 2][0] = r4[0]; bl[nb * 2][1] = r4[1];
                bl[nb * 2 + 1][0] = r4[2]; bl[nb * 2 + 1][1] = r4[3];
            }
#pragma unroll
            for (int mb = 0; mb < 2; mb++) {
                int rowm = m_base + mb * 16 + ((q & 1) * 8) + lr;
                int colk = kk + (q >> 1) * 8;
                uint32_t off = (uint32_t)(rowm * RS + colk) * 2;
                uint32_t ah[4], al[4];
                ldmatrix_x4(ah, bAh + off);
                ldmatrix_x4(al, bAl + off);
#pragma unroll
                for (int nb = 0; nb < 8; nb++) {
                    mma_bf16(acc[mb][nb], ah, bh[nb]);
                    mma_bf16(acc[mb][nb], ah, bl[nb]);
                    mma_bf16(acc[mb][nb], al, bh[nb]);
                }
            }
        }
        __syncthreads();
    }

#pragma unroll
    for (int mb = 0; mb < 2; mb++) {
        int row0 = m0 + m_base + mb * 16 + (lane >> 2);
#pragma unroll
        for (int nb = 0; nb < 8; nb++) {
            int col = n0 + n_base + nb * 8 + (lane & 3) * 2;
            if (col < 1024) {
                float2 rb = *(const float2*)(rr + col);
                store_split(g_qhi, g_qlo, (size_t)row0 * 1024 + col,
                            acc[mb][nb][0] + rb.x, acc[mb][nb][1] + rb.y);
                store_split(g_qhi, g_qlo, (size_t)(row0 + 8) * 1024 + col,
                            acc[mb][nb][2] + rb.x, acc[mb][nb][3] + rb.y);
            } else {
                int c2 = col - 1024;
                __half2 p0 = __floats2half2_rn(acc[mb][nb][0], acc[mb][nb][1]);
                __half2 p1 = __floats2half2_rn(acc[mb][nb][2], acc[mb][nb][3]);
                *(uint32_t*)(g_vf16 + (size_t)row0 * 1024 + c2) = *(uint32_t*)&p0;
                *(uint32_t*)(g_vf16 + (size_t)(row0 + 8) * 1024 + c2) = *(uint32_t*)&p1;
            }
        }
    }
#undef PREFETCH
}

// ---------------------------------------------------------------------------
// Tensor-core fused attention. Logit path (AC, G) bf16 2-split; P.V in fp16.
// Smem: K ping-pong 2x18432 (V fp16 reuses hi half) | pos 18432 |
//       Gs[64][2][68] fp32 (aliases A1 staging in prologue) | P fp16 | mk
// ---------------------------------------------------------------------------
#define SM_KBUF(bf) ((bf) * 18432)      // K: hi +0, lo +9216; V fp16: +0
#define SM_POSH 36864
#define SM_POSL 46080
#define SM_GS   55296
#define SM_PH   90112
#define SM_MK   99328
#define SM_ATTN_TOT 99584

__device__ __forceinline__ void g_block(uint32_t sb, float* Gs,
                                        const uint32_t (&a1h)[4][4],
                                        const uint32_t (&a1l)[4][4],
                                        int wid, int lane, int blk,
                                        const float* __restrict__ Eh, int base0) {
    const int lr = lane & 7, qd = lane >> 3;
    const int rowBg = (qd >> 1) * 8 + lr;
    const int rg = 16 * wid + (lane >> 2);
    const int cgl = (lane & 3) * 2;
    const int slot = blk & 1;
#pragma unroll
    for (int nb = 0; nb < 4; nb++) {
        float g0[4] = {0.f, 0.f, 0.f, 0.f}, g1[4] = {0.f, 0.f, 0.f, 0.f};
#pragma unroll
        for (int ks = 0; ks < 4; ks++) {
            int colB = ks * 16 + (qd & 1) * 8;
            uint32_t off = (uint32_t)((nb * 16 + rowBg) * RS + colB) * 2;
            uint32_t bh4[4], bl4[4];
            ldmatrix_x4(bh4, sb + SM_POSH + off);
            ldmatrix_x4(bl4, sb + SM_POSL + off);
            mma_bf16(g0, a1h[ks], bh4);
            mma_bf16(g0, a1h[ks], bl4);
            mma_bf16(g0, a1l[ks], bh4);
            mma_bf16(g1, a1h[ks], bh4 + 2);
            mma_bf16(g1, a1h[ks], bl4 + 2);
            mma_bf16(g1, a1l[ks], bh4 + 2);
        }
        int cg = nb * 16 + cgl;
        int gi = base0 + blk * 64 + cg;
        float e0 = Eh[min(gi, 1023)];
        float e1 = Eh[min(gi + 1, 1023)];
        float e8 = Eh[min(gi + 8, 1023)];
        float e9 = Eh[min(gi + 9, 1023)];
        int bq = rg * 136 + slot * 68;
        *(float2*)&Gs[bq + cg] = make_float2(g0[0] + e0, g0[1] + e1);
        *(float2*)&Gs[bq + 8 * 136 + cg] = make_float2(g0[2] + e0, g0[3] + e1);
        *(float2*)&Gs[bq + cg + 8] = make_float2(g1[0] + e8, g1[1] + e9);
        *(float2*)&Gs[bq + 8 * 136 + cg + 8] = make_float2(g1[2] + e8, g1[3] + e9);
    }
}

__global__ void __launch_bounds__(128) k_attn(const int* __restrict__ mask,
                                              float* __restrict__ out) {
    extern __shared__ char smc[];
    const uint32_t sb = smem_u32(smc);
    float* Gs = (float*)(smc + SM_GS);
    float* mk = (float*)(smc + SM_MK);

    const int tid = threadIdx.x;
    const int wid = tid >> 5, lane = tid & 31;
    const int lr = lane & 7, qd = lane >> 3;
    const int bh = blockIdx.y;
    const int b = bh >> 4, h = bh & 15;
    const int q0 = blockIdx.x * 64;
    const int base0 = 449 - q0;
    const float* Eh = g_E + h * 1024;

    // ---- prologue: stage A1 splits into (future) Gs region ----
    for (int i = tid; i < 512; i += 128) {
        int row = i >> 3, c = i & 7;
        size_t g = (size_t)(b * SEQ + q0 + row) * 1024 + h * 64 + c * 8;
        *(uint4*)(smc + SM_GS + (row * RS + c * 8) * 2) = *(const uint4*)(g_qhi + g);
        *(uint4*)(smc + SM_GS + 9216 + (row * RS + c * 8) * 2) = *(const uint4*)(g_qlo + g);
    }
    if (tid < 64) mk[tid] = (float)mask[b * SEQ + tid];
    __syncthreads();

    uint32_t a1h[4][4], a1l[4][4];
    {
        int rowA = 16 * wid + (qd & 1) * 8 + lr;
#pragma unroll
        for (int ks = 0; ks < 4; ks++) {
            int colA = ks * 16 + (qd >> 1) * 8;
            ldmatrix_x4(a1h[ks], sb + SM_GS + (uint32_t)(rowA * RS + colA) * 2);
            ldmatrix_x4(a1l[ks], sb + SM_GS + 9216 + (uint32_t)(rowA * RS + colA) * 2);
        }
    }

    // issue K(0) prefetch
    for (int i = tid; i < 512; i += 128) {
        int row = i >> 3, c = i & 7;
        size_t g = (size_t)(b * SEQ + row) * 1024 + h * 64 + c * 8;
        uint32_t d = sb + SM_KBUF(0) + (row * RS + c * 8) * 2;
        cp_async16(d, g_xhi + g);
        cp_async16(d + 9216, g_xlo + g);
    }
    CP_COMMIT();

    // ---- prologue: G blocks 0 and 1 ----
#pragma unroll
    for (int bi = 0; bi < 2; bi++) {
        int pbase = base0 + 64 * bi;
        for (int i = tid; i < 512; i += 128) {
            int row = i >> 3, c = i & 7;
            int j = pbase + row; if (j > 1023) j = 1023;
            size_t g = (size_t)j * 64 + c * 8;
            uint32_t d = (row * RS + c * 8) * 2;
            cp_async16(sb + SM_POSH + d, g_push + g);
            cp_async16(sb + SM_POSL + d, g_posl + g);
        }
        CP_COMMIT();
        CP_WAIT(0);
        __syncthreads();
        g_block(sb, Gs, a1h, a1l, wid, lane, bi, Eh, base0);
        __syncthreads();
    }

    float m0 = -1e30f, m1 = -1e30f, l0 = 0.f, l1 = 0.f;
    float O[8][4];
#pragma unroll
    for (int i = 0; i < 8; i++)
#pragma unroll
        for (int j = 0; j < 4; j++) O[i][j] = 0.f;

    const int rq0 = 16 * wid + (lane >> 2);
    const int rq1 = rq0 + 8;

    for (int kt = 0; kt < 8; kt++) {
        const int k0t = kt * 64;
        const uint32_t kb = sb + SM_KBUF(kt & 1);
        __syncthreads();

        // ---- AC = A1 @ K^T (K resident in kb) ----
        float acc[8][4];
#pragma unroll
        for (int i = 0; i < 8; i++)
#pragma unroll
            for (int j = 0; j < 4; j++) acc[i][j] = 0.f;
        {
            int rowBg = (qd >> 1) * 8 + lr;
#pragma unroll
            for (int nb = 0; nb < 4; nb++) {
#pragma unroll
                for (int ks = 0; ks < 4; ks++) {
                    int colB = ks * 16 + (qd & 1) * 8;
                    uint32_t off = (uint32_t)((nb * 16 + rowBg) * RS + colB) * 2;
                    uint32_t kh4[4], kl4[4];
                    ldmatrix_x4(kh4, kb + off);
                    ldmatrix_x4(kl4, kb + 9216 + off);
                    mma_bf16(acc[nb * 2], a1h[ks], kh4);
                    mma_bf16(acc[nb * 2], a1h[ks], kl4);
                    mma_bf16(acc[nb * 2], a1l[ks], kh4);
                    mma_bf16(acc[nb * 2 + 1], a1h[ks], kh4 + 2);
                    mma_bf16(acc[nb * 2 + 1], a1h[ks], kl4 + 2);
                    mma_bf16(acc[nb * 2 + 1], a1l[ks], kh4 + 2);
                }
            }
        }

        // ---- combine: S = AC + Gs(ring, E folded), mask, online softmax ----
        float rmax0 = -1e30f, rmax1 = -1e30f;
#pragma unroll
        for (int nt = 0; nt < 8; nt++) {
            int c0 = nt * 8 + (lane & 3) * 2;
#pragma unroll
            for (int e = 0; e < 4; e++) {
                int q = (e < 2) ? rq0 : rq1;
                int k = c0 + (e & 1);
                int gg = 64 * kt + k - q + 63;
                int slot = (gg >> 6) & 1;
                int col = gg & 63;
                float s = acc[nt][e] + Gs[q * 136 + slot * 68 + col];
                float mv = mk[k];
                s = s * mv - (1.f - mv) * 1e8f;
                acc[nt][e] = s;
                if (e < 2) rmax0 = fmaxf(rmax0, s); else rmax1 = fmaxf(rmax1, s);
            }
        }
        rmax0 = fmaxf(rmax0, __shfl_xor_sync(0xffffffffu, rmax0, 1));
        rmax0 = fmaxf(rmax0, __shfl_xor_sync(0xffffffffu, rmax0, 2));
        rmax1 = fmaxf(rmax1, __shfl_xor_sync(0xffffffffu, rmax1, 1));
        rmax1 = fmaxf(rmax1, __shfl_xor_sync(0xffffffffu, rmax1, 2));
        float mn0 = fmaxf(m0, rmax0), mn1 = fmaxf(m1, rmax1);
        float sc0 = __expf(m0 - mn0), sc1 = __expf(m1 - mn1);
        m0 = mn0; m1 = mn1;
        float rs0 = 0.f, rs1 = 0.f;
#pragma unroll
        for (int nt = 0; nt < 8; nt++) {
#pragma unroll
            for (int e = 0; e < 4; e++) {
                float p = __expf(acc[nt][e] - ((e < 2) ? mn0 : mn1));
                acc[nt][e] = p;
                if (e < 2) rs0 += p; else rs1 += p;
            }
        }
        rs0 += __shfl_xor_sync(0xffffffffu, rs0, 1);
        rs0 += __shfl_xor_sync(0xffffffffu, rs0, 2);
        rs1 += __shfl_xor_sync(0xffffffffu, rs1, 1);
        rs1 += __shfl_xor_sync(0xffffffffu, rs1, 2);
        l0 = l0 * sc0 + rs0;
        l1 = l1 * sc1 + rs1;
#pragma unroll
        for (int nt = 0; nt < 8; nt++) {
            O[nt][0] *= sc0; O[nt][1] *= sc0;
            O[nt][2] *= sc1; O[nt][3] *= sc1;
        }
        __syncthreads();   // K/Gs reads done; buffers reusable

        // ---- post phase: fire-and-forget cp.async (V fp16, next K, next pos) ----
        {
            // V tile: 64 rows x 64 fp16 = 512 chunks of 16B; 128 threads x 4 chunks
            int row = tid >> 1;              // 0..63
            int cbase = (tid & 1) * 4;       // chunk 0..3 or 4..7
#pragma unroll
            for (int cc = 0; cc < 4; cc++) {
                size_t g = (size_t)(b * SEQ + k0t + row) * 1024 + h * 64 + (cbase + cc) * 8;
                cp_async16(kb + (row * RS + (cbase + cc) * 8) * 2, g_vf16 + g);
            }
        }
        if (kt < 7) {
            const uint32_t kb2 = sb + SM_KBUF((kt + 1) & 1);
            for (int i = tid; i < 512; i += 128) {
                int row = i >> 3, c = i & 7;
                size_t g = (size_t)(b * SEQ + k0t + 64 + row) * 1024 + h * 64 + c * 8;
                uint32_t d = kb2 + (row * RS + c * 8) * 2;
                cp_async16(d, g_xhi + g);
                cp_async16(d + 9216, g_xlo + g);
            }
            int pbase = base0 + 64 * (kt + 2);
            for (int i = tid; i < 512; i += 128) {
                int row = i >> 3, c = i & 7;
                int j = pbase + row; if (j > 1023) j = 1023;
                size_t g = (size_t)j * 64 + c * 8;
                uint32_t d = (row * RS + c * 8) * 2;
                cp_async16(sb + SM_POSH + d, g_push + g);
                cp_async16(sb + SM_POSL + d, g_posl + g);
            }
            if (tid < 64) mk[tid] = (float)mask[b * SEQ + k0t + 64 + tid];
        }
        CP_COMMIT();

        // P -> fp16 into smem (overlaps cp.async flight)
#pragma unroll
        for (int nt = 0; nt < 8; nt++) {
            int c0 = nt * 8 + (lane & 3) * 2;
            __half2 p0 = __floats2half2_rn(acc[nt][0], acc[nt][1]);
            __half2 p1 = __floats2half2_rn(acc[nt][2], acc[nt][3]);
            *(uint32_t*)(smc + SM_PH + (rq0 * RS + c0) * 2) = *(uint32_t*)&p0;
            *(uint32_t*)(smc + SM_PH + (rq1 * RS + c0) * 2) = *(uint32_t*)&p1;
        }
        CP_WAIT(0);
        __syncthreads();

        // ---- O += P @ V (fp16 single) ; compute G block kt+2 ----
        {
            int rowP = 16 * wid + (qd & 1) * 8 + lr;
#pragma unroll
            for (int ks = 0; ks < 4; ks++) {
                int colP = ks * 16 + (qd >> 1) * 8;
                uint32_t ap[4];
                ldmatrix_x4(ap, sb + SM_PH + (uint32_t)(rowP * RS + colP) * 2);
                int rowV = ks * 16 + (qd & 1) * 8 + lr;
#pragma unroll
                for (int dt = 0; dt < 4; dt++) {
                    int colV = dt * 16 + (qd >> 1) * 8;
                    uint32_t off = (uint32_t)(rowV * RS + colV) * 2;
                    uint32_t vh[4];
                    ldmatrix_x4_t(vh, kb + off);
                    mma_f16(O[dt * 2], ap, vh);
                    mma_f16(O[dt * 2 + 1], ap, vh + 2);
                }
            }
        }
        if (kt < 7) g_block(sb, Gs, a1h, a1l, wid, lane, kt + 2, Eh, base0);
    }

    // ---- epilogue: out = O / l ----
    float li0 = 1.f / l0, li1 = 1.f / l1;
#pragma unroll
    for (int nt = 0; nt < 8; nt++) {
        int col = h * 64 + nt * 8 + (lane & 3) * 2;
        size_t r0o = (size_t)(b * SEQ + q0 + rq0) * DM + col;
        size_t r1o = (size_t)(b * SEQ + q0 + rq1) * DM + col;
        *(float2*)(out + r0o) = make_float2(O[nt][0] * li0, O[nt][1] * li0);
        *(float2*)(out + r1o) = make_float2(O[nt][2] * li1, O[nt][3] * li1);
    }
}

// ---------------------------------------------------------------------------
extern "C" void kernel_launch(void* const* d_in, const int* in_sizes, int n_in,
                              void* d_out, int out_size) {
    const float* x   = (const float*)d_in[0];
    const int*   msk = (const int*)d_in[1];
    const float* Wqv = (const float*)d_in[2];
    const float* rr  = (const float*)d_in[3];
    const float* rw  = (const float*)d_in[4];
    float* out = (float*)d_out;

    cudaFuncSetAttribute(k_attn, cudaFuncAttributeMaxDynamicSharedMemorySize, SM_ATTN_TOT);
    cudaFuncSetAttribute(k_mm, cudaFuncAttributeMaxDynamicSharedMemorySize, 3 * STAGE_B);

    k_cvt_x<<<4096, 256>>>(x);
    k_cvt_w<<<dim3(64, 32), dim3(32, 8)>>>(Wqv);
    k_pos<<<256, 256>>>();
    k_E<<<dim3(8, 16), 128>>>(rr, rw);
    k_mm<<<dim3(16, 32), 256, 3 * STAGE_B>>>(rr);
    k_attn<<<dim3(8, 128), 128, SM_ATTN_TOT>>>(msk, out);
}